// round 3
// baseline (speedup 1.0000x reference)
#include <cuda_runtime.h>
#include <math.h>

// Problem constants
#define B_  4
#define T_  4096
#define D_  512
#define BT_ (B_ * T_)          // 16384
#define N3_ (3 * D_)           // 1536
#define EPS_LN 1e-5f
#define SCALE_QK 0.04419417382415922f   // 1/sqrt(512)

// ---------------- scratch (device globals; no allocation allowed) -----------
__device__ float g_xn [ (long long)BT_ * D_  ];     //  33.5 MB  LN output
__device__ float g_qkv[ (long long)BT_ * N3_ ];     // 100.7 MB  QKV
__device__ float g_S  [ (long long)B_ * T_ * T_ ];  // 268.4 MB  scores/probs
__device__ float g_att[ (long long)BT_ * D_  ];     //  33.5 MB  attention out

// ---------------- LayerNorm: one block (128 thr) per row of 512 -------------
__global__ void ln_kernel(const float* __restrict__ x,
                          const float* __restrict__ gamma,
                          const float* __restrict__ beta,
                          float* __restrict__ xn)
{
    const long long row = blockIdx.x;
    const int tid = threadIdx.x;             // 0..127
    const float4* xr = (const float4*)(x + row * D_);
    float4 v = xr[tid];

    float s  = v.x + v.y + v.z + v.w;
    float ss = v.x*v.x + v.y*v.y + v.z*v.z + v.w*v.w;

    // warp reduce
    #pragma unroll
    for (int o = 16; o > 0; o >>= 1) {
        s  += __shfl_xor_sync(0xffffffffu, s,  o);
        ss += __shfl_xor_sync(0xffffffffu, ss, o);
    }
    __shared__ float rs[4], rss[4];
    if ((tid & 31) == 0) { rs[tid >> 5] = s; rss[tid >> 5] = ss; }
    __syncthreads();
    s  = rs[0]  + rs[1]  + rs[2]  + rs[3];
    ss = rss[0] + rss[1] + rss[2] + rss[3];

    const float mu   = s * (1.0f / D_);
    const float var  = ss * (1.0f / D_) - mu * mu;
    const float rstd = rsqrtf(var + EPS_LN);

    float4 g = ((const float4*)gamma)[tid];
    float4 b = ((const float4*)beta)[tid];
    float4 o;
    o.x = (v.x - mu) * rstd * g.x + b.x;
    o.y = (v.y - mu) * rstd * g.y + b.y;
    o.z = (v.z - mu) * rstd * g.z + b.z;
    o.w = (v.w - mu) * rstd * g.w + b.w;
    ((float4*)(xn + row * D_))[tid] = o;
}

// ---------------- SGEMM core: 128x128 block, BK=8, 256 thr, 8x8 microtile ---
#define BM 128
#define BN 128
#define BK 8
#define TM 8
#define TN 8

// C[M,N] = alpha * A[M,K] @ B[K,N]   (all row-major, per-z batch strides)
// causal_kbound: limit K to (m-tile end) -> causal P@V saving
__global__ __launch_bounds__(256, 2)
void sgemm_nn(const float* __restrict__ A, int lda, long long sA,
              const float* __restrict__ Bm, int ldb, long long sB,
              float* __restrict__ C, int ldc, long long sC,
              int M, int N, int K, float alpha, int causal_kbound)
{
    const int bx = blockIdx.x;   // n tile
    const int by = blockIdx.y;   // m tile
    const int bz = blockIdx.z;
    A  += (long long)bz * sA;
    Bm += (long long)bz * sB;
    C  += (long long)bz * sC;

    const int m0 = by * BM, n0 = bx * BN;
    int Keff = K;
    if (causal_kbound) { int kb = m0 + BM; Keff = kb < K ? kb : K; }

    __shared__ float As[BK][BM];
    __shared__ float Bs[BK][BN];

    const int tid = threadIdx.x;
    const int tx = tid & 15, ty = tid >> 4;

    const int arow = tid >> 1, acol = (tid & 1) * 4;   // A: 128 rows x 8 k
    const int brow = tid >> 5, bcol = (tid & 31) * 4;  // B: 8 k rows x 128 n

    const float* Aptr = A + (long long)(m0 + arow) * lda + acol;
    const float* Bptr = Bm + (long long)brow * ldb + n0 + bcol;

    float acc[TM][TN] = {};

    for (int k0 = 0; k0 < Keff; k0 += BK) {
        float4 av = *(const float4*)(Aptr + k0);
        As[acol + 0][arow] = av.x;
        As[acol + 1][arow] = av.y;
        As[acol + 2][arow] = av.z;
        As[acol + 3][arow] = av.w;
        float4 bv = *(const float4*)(Bptr + (long long)k0 * ldb);
        *(float4*)&Bs[brow][bcol] = bv;
        __syncthreads();

        #pragma unroll
        for (int kk = 0; kk < BK; kk++) {
            float a[TM], b[TN];
            *(float4*)&a[0] = *(const float4*)&As[kk][ty * TM];
            *(float4*)&a[4] = *(const float4*)&As[kk][ty * TM + 4];
            *(float4*)&b[0] = *(const float4*)&Bs[kk][tx * TN];
            *(float4*)&b[4] = *(const float4*)&Bs[kk][tx * TN + 4];
            #pragma unroll
            for (int i = 0; i < TM; i++)
                #pragma unroll
                for (int j = 0; j < TN; j++)
                    acc[i][j] += a[i] * b[j];
        }
        __syncthreads();
    }

    #pragma unroll
    for (int i = 0; i < TM; i++) {
        float* cr = C + (long long)(m0 + ty * TM + i) * ldc + n0 + tx * TN;
        float4 v0 = make_float4(alpha*acc[i][0], alpha*acc[i][1], alpha*acc[i][2], alpha*acc[i][3]);
        float4 v1 = make_float4(alpha*acc[i][4], alpha*acc[i][5], alpha*acc[i][6], alpha*acc[i][7]);
        *(float4*)(cr)     = v0;
        *(float4*)(cr + 4) = v1;
    }
}

// C[M,N] = alpha * A[M,K] @ B[N,K]^T  (scores). Skips tiles fully above diag.
__global__ __launch_bounds__(256, 2)
void sgemm_nt_causal(const float* __restrict__ A, int lda, long long sA,
                     const float* __restrict__ Bm, int ldb, long long sB,
                     float* __restrict__ C, int ldc, long long sC,
                     int K, float alpha)
{
    const int bx = blockIdx.x;   // n tile (key)
    const int by = blockIdx.y;   // m tile (query)
    if (bx > by) return;         // fully-masked tile: skip (softmax never reads)
    const int bz = blockIdx.z;
    A  += (long long)bz * sA;
    Bm += (long long)bz * sB;
    C  += (long long)bz * sC;

    const int m0 = by * BM, n0 = bx * BN;

    __shared__ float As[BK][BM];
    __shared__ float Bs[BK][BN];

    const int tid = threadIdx.x;
    const int tx = tid & 15, ty = tid >> 4;

    const int arow = tid >> 1, acol = (tid & 1) * 4;

    const float* Aptr = A + (long long)(m0 + arow) * lda + acol;
    const float* Bptr = Bm + (long long)(n0 + arow) * ldb + acol;

    float acc[TM][TN] = {};

    for (int k0 = 0; k0 < K; k0 += BK) {
        float4 av = *(const float4*)(Aptr + k0);
        As[acol + 0][arow] = av.x;
        As[acol + 1][arow] = av.y;
        As[acol + 2][arow] = av.z;
        As[acol + 3][arow] = av.w;
        float4 bv = *(const float4*)(Bptr + k0);
        Bs[acol + 0][arow] = bv.x;
        Bs[acol + 1][arow] = bv.y;
        Bs[acol + 2][arow] = bv.z;
        Bs[acol + 3][arow] = bv.w;
        __syncthreads();

        #pragma unroll
        for (int kk = 0; kk < BK; kk++) {
            float a[TM], b[TN];
            *(float4*)&a[0] = *(const float4*)&As[kk][ty * TM];
            *(float4*)&a[4] = *(const float4*)&As[kk][ty * TM + 4];
            *(float4*)&b[0] = *(const float4*)&Bs[kk][tx * TN];
            *(float4*)&b[4] = *(const float4*)&Bs[kk][tx * TN + 4];
            #pragma unroll
            for (int i = 0; i < TM; i++)
                #pragma unroll
                for (int j = 0; j < TN; j++)
                    acc[i][j] += a[i] * b[j];
        }
        __syncthreads();
    }

    #pragma unroll
    for (int i = 0; i < TM; i++) {
        float* cr = C + (long long)(m0 + ty * TM + i) * ldc + n0 + tx * TN;
        float4 v0 = make_float4(alpha*acc[i][0], alpha*acc[i][1], alpha*acc[i][2], alpha*acc[i][3]);
        float4 v1 = make_float4(alpha*acc[i][4], alpha*acc[i][5], alpha*acc[i][6], alpha*acc[i][7]);
        *(float4*)(cr)     = v0;
        *(float4*)(cr + 4) = v1;
    }
}

// ---------------- causal row softmax: one block (256 thr) per row -----------
__global__ void softmax_kernel(float* __restrict__ S)
{
    const long long row = blockIdx.x;            // 0..BT-1
    const int b = (int)(row >> 12);              // row / T
    const int t = (int)(row & (T_ - 1));
    float* p = S + ((long long)b * T_ + t) * T_;
    const int n = t + 1;                         // valid entries: s <= t
    const int tid = threadIdx.x;

    __shared__ float redm[8], reds[8];

    // 1. max over valid entries
    float m = -3.402823466e38f;
    for (int i = tid; i < n; i += 256) m = fmaxf(m, p[i]);
    #pragma unroll
    for (int o = 16; o > 0; o >>= 1) m = fmaxf(m, __shfl_xor_sync(0xffffffffu, m, o));
    if ((tid & 31) == 0) redm[tid >> 5] = m;
    __syncthreads();
    m = redm[0];
    #pragma unroll
    for (int i = 1; i < 8; i++) m = fmaxf(m, redm[i]);

    // 2. exp + sum, store exp in place
    float s = 0.f;
    for (int i = tid; i < n; i += 256) {
        float e = __expf(p[i] - m);
        p[i] = e;
        s += e;
    }
    #pragma unroll
    for (int o = 16; o > 0; o >>= 1) s += __shfl_xor_sync(0xffffffffu, s, o);
    if ((tid & 31) == 0) reds[tid >> 5] = s;
    __syncthreads();
    s = reds[0] + reds[1] + reds[2] + reds[3] + reds[4] + reds[5] + reds[6] + reds[7];
    const float inv = 1.0f / s;

    // 3. normalize valid entries, zero-fill masked tail (so P@V reads zeros)
    for (int i = tid; i < n; i += 256) p[i] *= inv;
    for (int i = n + tid; i < T_; i += 256) p[i] = 0.f;
}

// ---------------- launch ----------------------------------------------------
extern "C" void kernel_launch(void* const* d_in, const int* in_sizes, int n_in,
                              void* d_out, int out_size)
{
    const float* x     = (const float*)d_in[0];
    // d_in[1] = mask (causality implemented directly)
    const float* gamma = (const float*)d_in[2];
    const float* beta  = (const float*)d_in[3];
    const float* Wqkv  = (const float*)d_in[4];
    const float* Wproj = (const float*)d_in[5];
    float* out = (float*)d_out;

    float *xn, *qkv, *S, *att;
    cudaGetSymbolAddress((void**)&xn,  g_xn);
    cudaGetSymbolAddress((void**)&qkv, g_qkv);
    cudaGetSymbolAddress((void**)&S,   g_S);
    cudaGetSymbolAddress((void**)&att, g_att);

    // 1. LayerNorm
    ln_kernel<<<BT_, 128>>>(x, gamma, beta, xn);

    // 2. QKV projection: [16384,512] @ [512,1536]
    sgemm_nn<<<dim3(N3_ / BN, BT_ / BM, 1), 256>>>(
        xn, D_, 0, Wqkv, N3_, 0, qkv, N3_, 0,
        BT_, N3_, D_, 1.0f, 0);

    // 3. scores: per batch, Q @ K^T * scale (causal tile skip)
    sgemm_nt_causal<<<dim3(T_ / BN, T_ / BM, B_), 256>>>(
        qkv + 0,   N3_, (long long)T_ * N3_,     // Q
        qkv + D_,  N3_, (long long)T_ * N3_,     // K
        S, T_, (long long)T_ * T_,
        D_, SCALE_QK);

    // 4. causal row softmax (zero-fills masked tail)
    softmax_kernel<<<BT_, 256>>>(S);

    // 5. P @ V per batch, K-loop bounded at diagonal
    sgemm_nn<<<dim3(D_ / BN, T_ / BM, B_), 256>>>(
        S, T_, (long long)T_ * T_,
        qkv + 2 * D_, N3_, (long long)T_ * N3_,  // V
        att, D_, (long long)T_ * D_,
        T_, D_, T_, 1.0f, /*causal_kbound=*/1);

    // 6. output projection: [16384,512] @ [512,512]
    sgemm_nn<<<dim3(D_ / BN, BT_ / BM, 1), 256>>>(
        att, D_, 0, Wproj, D_, 0, out, D_, 0,
        BT_, D_, D_, 1.0f, 0);
}

// round 4
// speedup vs baseline: 1.0013x; 1.0013x over previous
#include <cuda_runtime.h>
#include <math.h>

// Problem constants
#define B_  4
#define T_  4096
#define D_  512
#define BT_ (B_ * T_)          // 16384
#define N3_ (3 * D_)           // 1536
#define EPS_LN 1e-5f
#define SCALE_QK 0.04419417382415922f   // 1/sqrt(512)

// ---------------- scratch (device globals; no allocation allowed) -----------
__device__ float g_xn [ (long long)BT_ * D_  ];     //  33.5 MB  LN output
__device__ float g_qkv[ (long long)BT_ * N3_ ];     // 100.7 MB  QKV
__device__ float g_S  [ (long long)B_ * T_ * T_ ];  // 268.4 MB  scores/probs
__device__ float g_att[ (long long)BT_ * D_  ];     //  33.5 MB  attention out

// ---------------- packed f32x2 helpers (Blackwell FFMA2 path) ---------------
__device__ __forceinline__ unsigned long long pk2dup(float v) {
    unsigned long long r;
    asm("mov.b64 %0, {%1, %1};" : "=l"(r) : "f"(v));
    return r;
}
__device__ __forceinline__ void fma2(unsigned long long &d,
                                     unsigned long long a,
                                     unsigned long long b) {
    asm("fma.rn.f32x2 %0, %1, %2, %3;" : "=l"(d) : "l"(a), "l"(b), "l"(d));
}
__device__ __forceinline__ void unpk2(float &lo, float &hi, unsigned long long v) {
    asm("mov.b64 {%0, %1}, %2;" : "=f"(lo), "=f"(hi) : "l"(v));
}

// ---------------- LayerNorm: one block (128 thr) per row of 512 -------------
__global__ void ln_kernel(const float* __restrict__ x,
                          const float* __restrict__ gamma,
                          const float* __restrict__ beta,
                          float* __restrict__ xn)
{
    const long long row = blockIdx.x;
    const int tid = threadIdx.x;             // 0..127
    const float4* xr = (const float4*)(x + row * D_);
    float4 v = xr[tid];

    float s  = v.x + v.y + v.z + v.w;
    float ss = v.x*v.x + v.y*v.y + v.z*v.z + v.w*v.w;

    #pragma unroll
    for (int o = 16; o > 0; o >>= 1) {
        s  += __shfl_xor_sync(0xffffffffu, s,  o);
        ss += __shfl_xor_sync(0xffffffffu, ss, o);
    }
    __shared__ float rs[4], rss[4];
    if ((tid & 31) == 0) { rs[tid >> 5] = s; rss[tid >> 5] = ss; }
    __syncthreads();
    s  = rs[0]  + rs[1]  + rs[2]  + rs[3];
    ss = rss[0] + rss[1] + rss[2] + rss[3];

    const float mu   = s * (1.0f / D_);
    const float var  = ss * (1.0f / D_) - mu * mu;
    const float rstd = rsqrtf(var + EPS_LN);

    float4 g = ((const float4*)gamma)[tid];
    float4 b = ((const float4*)beta)[tid];
    float4 o;
    o.x = (v.x - mu) * rstd * g.x + b.x;
    o.y = (v.y - mu) * rstd * g.y + b.y;
    o.z = (v.z - mu) * rstd * g.z + b.z;
    o.w = (v.w - mu) * rstd * g.w + b.w;
    ((float4*)(xn + row * D_))[tid] = o;
}

// ---------------- SGEMM core: 128x128 block, BK=8, 256 thr, 8x8 microtile ---
#define BM 128
#define BN 128
#define BK 8
#define TM 8
#define TN 8

// C[M,N] = alpha * A[M,K] @ B[K,N]   (all row-major, per-z batch strides)
// causal_kbound: limit K to (m-tile end) -> causal P@V saving
__global__ __launch_bounds__(256, 2)
void sgemm_nn(const float* __restrict__ A, int lda, long long sA,
              const float* __restrict__ Bm, int ldb, long long sB,
              float* __restrict__ C, int ldc, long long sC,
              int M, int N, int K, float alpha, int causal_kbound)
{
    const int bx = blockIdx.x;   // n tile
    const int by = blockIdx.y;   // m tile
    const int bz = blockIdx.z;
    A  += (long long)bz * sA;
    Bm += (long long)bz * sB;
    C  += (long long)bz * sC;

    const int m0 = by * BM, n0 = bx * BN;
    int Keff = K;
    if (causal_kbound) { int kb = m0 + BM; Keff = kb < K ? kb : K; }

    __shared__ __align__(16) float As[BK][BM];
    __shared__ __align__(16) float Bs[BK][BN];

    const int tid = threadIdx.x;
    const int tx = tid & 15, ty = tid >> 4;

    const int arow = tid >> 1, acol = (tid & 1) * 4;   // A: 128 rows x 8 k
    const int brow = tid >> 5, bcol = (tid & 31) * 4;  // B: 8 k rows x 128 n

    const float* Aptr = A + (long long)(m0 + arow) * lda + acol;
    const float* Bptr = Bm + (long long)brow * ldb + n0 + bcol;

    unsigned long long acc2[TM][TN/2] = {};

    for (int k0 = 0; k0 < Keff; k0 += BK) {
        float4 av = *(const float4*)(Aptr + k0);
        As[acol + 0][arow] = av.x;
        As[acol + 1][arow] = av.y;
        As[acol + 2][arow] = av.z;
        As[acol + 3][arow] = av.w;
        float4 bv = *(const float4*)(Bptr + (long long)k0 * ldb);
        *(float4*)&Bs[brow][bcol] = bv;
        __syncthreads();

        #pragma unroll
        for (int kk = 0; kk < BK; kk++) {
            float a[TM];
            *(float4*)&a[0] = *(const float4*)&As[kk][ty * TM];
            *(float4*)&a[4] = *(const float4*)&As[kk][ty * TM + 4];
            const ulonglong2* bq = (const ulonglong2*)&Bs[kk][tx * TN];
            ulonglong2 b01 = bq[0], b23 = bq[1];
            unsigned long long bp[TN/2] = { b01.x, b01.y, b23.x, b23.y };
            unsigned long long ap[TM];
            #pragma unroll
            for (int i = 0; i < TM; i++) ap[i] = pk2dup(a[i]);
            #pragma unroll
            for (int i = 0; i < TM; i++)
                #pragma unroll
                for (int j = 0; j < TN/2; j++)
                    fma2(acc2[i][j], ap[i], bp[j]);
        }
        __syncthreads();
    }

    #pragma unroll
    for (int i = 0; i < TM; i++) {
        float r[TN];
        #pragma unroll
        for (int j = 0; j < TN/2; j++) unpk2(r[2*j], r[2*j+1], acc2[i][j]);
        float* cr = C + (long long)(m0 + ty * TM + i) * ldc + n0 + tx * TN;
        float4 v0 = make_float4(alpha*r[0], alpha*r[1], alpha*r[2], alpha*r[3]);
        float4 v1 = make_float4(alpha*r[4], alpha*r[5], alpha*r[6], alpha*r[7]);
        *(float4*)(cr)     = v0;
        *(float4*)(cr + 4) = v1;
    }
}

// C[M,N] = alpha * A[M,K] @ B[N,K]^T  (scores). Skips tiles fully above diag.
__global__ __launch_bounds__(256, 2)
void sgemm_nt_causal(const float* __restrict__ A, int lda, long long sA,
                     const float* __restrict__ Bm, int ldb, long long sB,
                     float* __restrict__ C, int ldc, long long sC,
                     int K, float alpha)
{
    const int bx = blockIdx.x;   // n tile (key)
    const int by = blockIdx.y;   // m tile (query)
    if (bx > by) return;         // fully-masked tile: skip (softmax never reads)
    const int bz = blockIdx.z;
    A  += (long long)bz * sA;
    Bm += (long long)bz * sB;
    C  += (long long)bz * sC;

    const int m0 = by * BM, n0 = bx * BN;

    __shared__ __align__(16) float As[BK][BM];
    __shared__ __align__(16) float Bs[BK][BN];

    const int tid = threadIdx.x;
    const int tx = tid & 15, ty = tid >> 4;

    const int arow = tid >> 1, acol = (tid & 1) * 4;

    const float* Aptr = A + (long long)(m0 + arow) * lda + acol;
    const float* Bptr = Bm + (long long)(n0 + arow) * ldb + acol;

    unsigned long long acc2[TM][TN/2] = {};

    for (int k0 = 0; k0 < K; k0 += BK) {
        float4 av = *(const float4*)(Aptr + k0);
        As[acol + 0][arow] = av.x;
        As[acol + 1][arow] = av.y;
        As[acol + 2][arow] = av.z;
        As[acol + 3][arow] = av.w;
        float4 bv = *(const float4*)(Bptr + k0);
        Bs[acol + 0][arow] = bv.x;
        Bs[acol + 1][arow] = bv.y;
        Bs[acol + 2][arow] = bv.z;
        Bs[acol + 3][arow] = bv.w;
        __syncthreads();

        #pragma unroll
        for (int kk = 0; kk < BK; kk++) {
            float a[TM];
            *(float4*)&a[0] = *(const float4*)&As[kk][ty * TM];
            *(float4*)&a[4] = *(const float4*)&As[kk][ty * TM + 4];
            const ulonglong2* bq = (const ulonglong2*)&Bs[kk][tx * TN];
            ulonglong2 b01 = bq[0], b23 = bq[1];
            unsigned long long bp[TN/2] = { b01.x, b01.y, b23.x, b23.y };
            unsigned long long ap[TM];
            #pragma unroll
            for (int i = 0; i < TM; i++) ap[i] = pk2dup(a[i]);
            #pragma unroll
            for (int i = 0; i < TM; i++)
                #pragma unroll
                for (int j = 0; j < TN/2; j++)
                    fma2(acc2[i][j], ap[i], bp[j]);
        }
        __syncthreads();
    }

    #pragma unroll
    for (int i = 0; i < TM; i++) {
        float r[TN];
        #pragma unroll
        for (int j = 0; j < TN/2; j++) unpk2(r[2*j], r[2*j+1], acc2[i][j]);
        float* cr = C + (long long)(m0 + ty * TM + i) * ldc + n0 + tx * TN;
        float4 v0 = make_float4(alpha*r[0], alpha*r[1], alpha*r[2], alpha*r[3]);
        float4 v1 = make_float4(alpha*r[4], alpha*r[5], alpha*r[6], alpha*r[7]);
        *(float4*)(cr)     = v0;
        *(float4*)(cr + 4) = v1;
    }
}

// ---------------- causal row softmax: one block (256 thr) per row -----------
__global__ void softmax_kernel(float* __restrict__ S)
{
    const long long row = blockIdx.x;            // 0..BT-1
    const int b = (int)(row >> 12);              // row / T
    const int t = (int)(row & (T_ - 1));
    float* p = S + ((long long)b * T_ + t) * T_;
    const int n = t + 1;                         // valid entries: s <= t
    const int tid = threadIdx.x;

    __shared__ float redm[8], reds[8];

    // 1. max over valid entries
    float m = -3.402823466e38f;
    for (int i = tid; i < n; i += 256) m = fmaxf(m, p[i]);
    #pragma unroll
    for (int o = 16; o > 0; o >>= 1) m = fmaxf(m, __shfl_xor_sync(0xffffffffu, m, o));
    if ((tid & 31) == 0) redm[tid >> 5] = m;
    __syncthreads();
    m = redm[0];
    #pragma unroll
    for (int i = 1; i < 8; i++) m = fmaxf(m, redm[i]);

    // 2. exp + sum, store exp in place
    float s = 0.f;
    for (int i = tid; i < n; i += 256) {
        float e = __expf(p[i] - m);
        p[i] = e;
        s += e;
    }
    #pragma unroll
    for (int o = 16; o > 0; o >>= 1) s += __shfl_xor_sync(0xffffffffu, s, o);
    if ((tid & 31) == 0) reds[tid >> 5] = s;
    __syncthreads();
    s = reds[0] + reds[1] + reds[2] + reds[3] + reds[4] + reds[5] + reds[6] + reds[7];
    const float inv = 1.0f / s;

    // 3. normalize valid entries, zero-fill masked tail (so P@V reads zeros)
    for (int i = tid; i < n; i += 256) p[i] *= inv;
    for (int i = n + tid; i < T_; i += 256) p[i] = 0.f;
}

// ---------------- launch ----------------------------------------------------
extern "C" void kernel_launch(void* const* d_in, const int* in_sizes, int n_in,
                              void* d_out, int out_size)
{
    const float* x     = (const float*)d_in[0];
    // d_in[1] = mask (causality implemented directly)
    const float* gamma = (const float*)d_in[2];
    const float* beta  = (const float*)d_in[3];
    const float* Wqkv  = (const float*)d_in[4];
    const float* Wproj = (const float*)d_in[5];
    float* out = (float*)d_out;

    float *xn, *qkv, *S, *att;
    cudaGetSymbolAddress((void**)&xn,  g_xn);
    cudaGetSymbolAddress((void**)&qkv, g_qkv);
    cudaGetSymbolAddress((void**)&S,   g_S);
    cudaGetSymbolAddress((void**)&att, g_att);

    // 1. LayerNorm
    ln_kernel<<<BT_, 128>>>(x, gamma, beta, xn);

    // 2. QKV projection: [16384,512] @ [512,1536]
    sgemm_nn<<<dim3(N3_ / BN, BT_ / BM, 1), 256>>>(
        xn, D_, 0, Wqkv, N3_, 0, qkv, N3_, 0,
        BT_, N3_, D_, 1.0f, 0);

    // 3. scores: per batch, Q @ K^T * scale (causal tile skip)
    sgemm_nt_causal<<<dim3(T_ / BN, T_ / BM, B_), 256>>>(
        qkv + 0,   N3_, (long long)T_ * N3_,     // Q
        qkv + D_,  N3_, (long long)T_ * N3_,     // K
        S, T_, (long long)T_ * T_,
        D_, SCALE_QK);

    // 4. causal row softmax (zero-fills masked tail)
    softmax_kernel<<<BT_, 256>>>(S);

    // 5. P @ V per batch, K-loop bounded at diagonal
    sgemm_nn<<<dim3(D_ / BN, T_ / BM, B_), 256>>>(
        S, T_, (long long)T_ * T_,
        qkv + 2 * D_, N3_, (long long)T_ * N3_,  // V
        att, D_, (long long)T_ * D_,
        T_, D_, T_, 1.0f, /*causal_kbound=*/1);

    // 6. output projection: [16384,512] @ [512,512]
    sgemm_nn<<<dim3(D_ / BN, BT_ / BM, 1), 256>>>(
        att, D_, 0, Wproj, D_, 0, out, D_, 0,
        BT_, D_, D_, 1.0f, 0);
}

// round 8
// speedup vs baseline: 2.2657x; 2.2627x over previous
#include <cuda_runtime.h>
#include <cuda_bf16.h>
#include <cstdint>
#include <math.h>

// Problem constants
#define B_  4
#define T_  4096
#define D_  512
#define BT_ (B_ * T_)          // 16384
#define N3_ (3 * D_)           // 1536
#define EPS_LN 1e-5f
#define SCALE_QK 0.04419417382415922f   // 1/sqrt(512)

typedef long long ll;
typedef __nv_bfloat16 bf16;

// ---------------- scratch (device globals) ----------------------------------
__device__ bf16  g_xn_h [(ll)BT_ * D_];
__device__ bf16  g_xn_l [(ll)BT_ * D_];
__device__ bf16  g_wqkvT_h [(ll)N3_ * D_];
__device__ bf16  g_wqkvT_l [(ll)N3_ * D_];
__device__ bf16  g_wprojT_h[(ll)D_ * D_];
__device__ bf16  g_wprojT_l[(ll)D_ * D_];
__device__ bf16  g_qkv_h[(ll)BT_ * N3_];
__device__ bf16  g_qkv_l[(ll)BT_ * N3_];
__device__ bf16  g_vt_h [(ll)B_ * D_ * T_];
__device__ bf16  g_vt_l [(ll)B_ * D_ * T_];
__device__ float g_S    [(ll)B_ * T_ * T_];
__device__ bf16  g_P_h  [(ll)B_ * T_ * T_];
__device__ bf16  g_P_l  [(ll)B_ * T_ * T_];
__device__ bf16  g_att_h[(ll)BT_ * D_];
__device__ bf16  g_att_l[(ll)BT_ * D_];

// ---------------- PTX helpers (all base sm_103-safe) -------------------------
__device__ __forceinline__ uint32_t smem_u32(const void* p) {
    uint32_t a;
    asm("{ .reg .u64 t; cvta.to.shared.u64 t, %1; cvt.u32.u64 %0, t; }" : "=r"(a) : "l"(p));
    return a;
}
__device__ __forceinline__ void cp16(uint32_t d, const void* g) {
    asm volatile("cp.async.cg.shared.global [%0], [%1], 16;" :: "r"(d), "l"(g) : "memory");
}
#define CP_COMMIT() asm volatile("cp.async.commit_group;" ::: "memory")
#define CP_WAIT(n)  asm volatile("cp.async.wait_group %0;" :: "n"(n) : "memory")

#define LDSM4(r0, r1, r2, r3, a) \
    asm volatile("ldmatrix.sync.aligned.m8n8.x4.shared.b16 {%0,%1,%2,%3}, [%4];" \
        : "=r"(r0), "=r"(r1), "=r"(r2), "=r"(r3) : "r"(a))

#define MMA16816(d, a, b) \
    asm volatile("mma.sync.aligned.m16n8k16.row.col.f32.bf16.bf16.f32 " \
        "{%0,%1,%2,%3}, {%4,%5,%6,%7}, {%8,%9}, {%0,%1,%2,%3};" \
        : "+f"((d)[0]), "+f"((d)[1]), "+f"((d)[2]), "+f"((d)[3]) \
        : "r"((a)[0]), "r"((a)[1]), "r"((a)[2]), "r"((a)[3]), "r"((b)[0]), "r"((b)[1]))

__device__ __forceinline__ void split_bf16(float v, bf16& h, bf16& l) {
    h = __float2bfloat16_rn(v);
    l = __float2bfloat16_rn(v - __bfloat162float(h));
}

// ---------------- LayerNorm -> hi/lo bf16 ------------------------------------
__global__ void ln_kernel(const float* __restrict__ x,
                          const float* __restrict__ gamma,
                          const float* __restrict__ beta,
                          bf16* __restrict__ xh, bf16* __restrict__ xl)
{
    const ll row = blockIdx.x;
    const int tid = threadIdx.x;             // 0..127
    float4 v = ((const float4*)(x + row * D_))[tid];

    float s  = v.x + v.y + v.z + v.w;
    float ss = v.x*v.x + v.y*v.y + v.z*v.z + v.w*v.w;
    #pragma unroll
    for (int o = 16; o > 0; o >>= 1) {
        s  += __shfl_xor_sync(0xffffffffu, s,  o);
        ss += __shfl_xor_sync(0xffffffffu, ss, o);
    }
    __shared__ float rs[4], rss[4];
    if ((tid & 31) == 0) { rs[tid >> 5] = s; rss[tid >> 5] = ss; }
    __syncthreads();
    s  = rs[0] + rs[1] + rs[2] + rs[3];
    ss = rss[0] + rss[1] + rss[2] + rss[3];

    const float mu   = s * (1.0f / D_);
    const float var  = ss * (1.0f / D_) - mu * mu;
    const float rstd = rsqrtf(var + EPS_LN);

    float4 g = ((const float4*)gamma)[tid];
    float4 b = ((const float4*)beta)[tid];
    float o0 = (v.x - mu) * rstd * g.x + b.x;
    float o1 = (v.y - mu) * rstd * g.y + b.y;
    float o2 = (v.z - mu) * rstd * g.z + b.z;
    float o3 = (v.w - mu) * rstd * g.w + b.w;

    bf16 h[4], l[4];
    split_bf16(o0, h[0], l[0]); split_bf16(o1, h[1], l[1]);
    split_bf16(o2, h[2], l[2]); split_bf16(o3, h[3], l[3]);
    *(ulonglong1*)(xh + row * D_ + tid * 4) = *(ulonglong1*)h;
    *(ulonglong1*)(xl + row * D_ + tid * 4) = *(ulonglong1*)l;
}

// ---------------- weight transpose-convert: W[K,N] f32 -> Wt[N,K] hi/lo ------
__global__ void wtrans_kernel(const float* __restrict__ W, int K, int N,
                              bf16* __restrict__ Th, bf16* __restrict__ Tl)
{
    __shared__ float t[32][33];
    const int n0 = blockIdx.x * 32, k0 = blockIdx.y * 32;
    const int tx = threadIdx.x, ty = threadIdx.y;
    #pragma unroll
    for (int i = 0; i < 32; i += 8)
        t[ty + i][tx] = W[(ll)(k0 + ty + i) * N + n0 + tx];
    __syncthreads();
    #pragma unroll
    for (int i = 0; i < 32; i += 8) {
        float v = t[tx][ty + i];
        bf16 h, l; split_bf16(v, h, l);
        Th[(ll)(n0 + ty + i) * K + k0 + tx] = h;
        Tl[(ll)(n0 + ty + i) * K + k0 + tx] = l;
    }
}

// ---------------- V transpose: qkv hi/lo [BT,1536] -> VT hi/lo [B,512,T] -----
__global__ void vtrans_kernel(const bf16* __restrict__ qh, const bf16* __restrict__ ql,
                              bf16* __restrict__ vh, bf16* __restrict__ vl)
{
    __shared__ bf16 th[32][33], tl[32][33];
    const int s0 = blockIdx.x * 32, c0 = blockIdx.y * 32, b = blockIdx.z;
    const int tx = threadIdx.x, ty = threadIdx.y;
    const ll qb = ((ll)b * T_) * N3_ + 2 * D_;
    #pragma unroll
    for (int i = 0; i < 32; i += 8) {
        th[ty + i][tx] = qh[qb + (ll)(s0 + ty + i) * N3_ + c0 + tx];
        tl[ty + i][tx] = ql[qb + (ll)(s0 + ty + i) * N3_ + c0 + tx];
    }
    __syncthreads();
    const ll vb = (ll)b * D_ * T_;
    #pragma unroll
    for (int i = 0; i < 32; i += 8) {
        vh[vb + (ll)(c0 + ty + i) * T_ + s0 + tx] = th[tx][ty + i];
        vl[vb + (ll)(c0 + ty + i) * T_ + s0 + tx] = tl[tx][ty + i];
    }
}

// ---------------- bf16x3 NT GEMM on mma.sync (HMMA) --------------------------
// C[M,N] = alpha * (Ah+Al)[M,K] @ (Bh+Bl)[N,K]^T
// flags: 1 = causal tile skip (bx>by), 2 = causal kbound, 4 = bf16 hi/lo output
// Tile: CTA 128x128, BK=32, 8 warps (2x4), warp tile 64x32, 4x4 m16n8k16.
#define MAT_B 8192                // 128 rows * 32 k * 2B
#define STG_B (4 * MAT_B)         // Ah, Al, Bh, Bl
#define GSMEM (2 * STG_B)         // 64 KB, double buffered

__global__ __launch_bounds__(256, 1)
void gemm_mma(const bf16* __restrict__ Ah, const bf16* __restrict__ Al, int lda, ll sA,
              const bf16* __restrict__ Bh, const bf16* __restrict__ Bl, int ldb, ll sB,
              float* __restrict__ Cf, bf16* __restrict__ Ch, bf16* __restrict__ Cl,
              int ldc, ll sC, int K, float alpha, int flags)
{
    const int bx = blockIdx.x, by = blockIdx.y, bz = blockIdx.z;
    if ((flags & 1) && bx > by) return;

    extern __shared__ char smem[];
    const uint32_t sbase = smem_u32(smem);
    const int tid = threadIdx.x;
    const int wid = tid >> 5, lane = tid & 31;
    const int wm = wid >> 2, wn = wid & 3;

    const int m0 = by * 128, n0 = bx * 128;
    int Keff = K;
    if (flags & 2) { int kb = m0 + 128; Keff = kb < K ? kb : K; }
    const int NK = Keff / 32;

    const char* srcAh = (const char*)(Ah + (ll)bz * sA + (ll)m0 * lda);
    const char* srcAl = (const char*)(Al + (ll)bz * sA + (ll)m0 * lda);
    const char* srcBh = (const char*)(Bh + (ll)bz * sB + (ll)n0 * ldb);
    const char* srcBl = (const char*)(Bl + (ll)bz * sB + (ll)n0 * ldb);
    const ll strA = (ll)lda * 2, strB = (ll)ldb * 2;

    // loader: 512 16B chunks per matrix per stage; thread does 2 chunks/matrix
    const int cid0 = tid * 2;
    const int lrow0 = cid0 >> 2, lc0 = cid0 & 3;
    const int lrow1 = (cid0 + 1) >> 2, lc1 = (cid0 + 1) & 3;
    const uint32_t ldoff0 = lrow0 * 64 + (lc0 ^ ((lrow0 >> 1) & 3)) * 16;
    const uint32_t ldoff1 = lrow1 * 64 + (lc1 ^ ((lrow1 >> 1) & 3)) * 16;

    auto load_stage = [&](int s, int k0) {
        const uint32_t db = sbase + s * STG_B;
        const ll ko = (ll)k0 * 2;
        const ll gA0 = (ll)lrow0 * strA + ko + lc0 * 16;
        const ll gA1 = (ll)lrow1 * strA + ko + lc1 * 16;
        const ll gB0 = (ll)lrow0 * strB + ko + lc0 * 16;
        const ll gB1 = (ll)lrow1 * strB + ko + lc1 * 16;
        cp16(db + 0 * MAT_B + ldoff0, srcAh + gA0);
        cp16(db + 0 * MAT_B + ldoff1, srcAh + gA1);
        cp16(db + 1 * MAT_B + ldoff0, srcAl + gA0);
        cp16(db + 1 * MAT_B + ldoff1, srcAl + gA1);
        cp16(db + 2 * MAT_B + ldoff0, srcBh + gB0);
        cp16(db + 2 * MAT_B + ldoff1, srcBh + gB1);
        cp16(db + 3 * MAT_B + ldoff0, srcBl + gB0);
        cp16(db + 3 * MAT_B + ldoff1, srcBl + gB1);
    };

    // ldmatrix per-thread offsets within a matrix region (for ks=0; ^32 for ks=1)
    uint32_t aOff[4], bOff[2];
    {
        const int l15 = lane & 15, l4 = lane >> 4;
        #pragma unroll
        for (int mt = 0; mt < 4; mt++) {
            int r = wm * 64 + mt * 16 + l15;
            aOff[mt] = r * 64 + ((l4 ^ ((r >> 1) & 3)) * 16);
        }
        const int l7 = lane & 7, l3 = (lane >> 3) & 1;
        #pragma unroll
        for (int p = 0; p < 2; p++) {
            int r = wn * 32 + (p * 2 + l4) * 8 + l7;
            bOff[p] = r * 64 + ((l3 ^ ((r >> 1) & 3)) * 16);
        }
    }

    float acc[4][4][4] = {};

    load_stage(0, 0);
    CP_COMMIT();

    for (int c = 0; c < NK; ++c) {
        const int s = c & 1;
        if (c + 1 < NK) {
            load_stage((c + 1) & 1, (c + 1) * 32);
            CP_COMMIT();
            CP_WAIT(1);
        } else {
            CP_WAIT(0);
        }
        __syncthreads();

        const uint32_t sb = sbase + s * STG_B;
        #pragma unroll
        for (int ks = 0; ks < 2; ks++) {
            const uint32_t kx = ks * 32;
            uint32_t ah[4][4], al[4][4];
            #pragma unroll
            for (int mt = 0; mt < 4; mt++) {
                LDSM4(ah[mt][0], ah[mt][1], ah[mt][2], ah[mt][3], sb + 0 * MAT_B + (aOff[mt] ^ kx));
                LDSM4(al[mt][0], al[mt][1], al[mt][2], al[mt][3], sb + 1 * MAT_B + (aOff[mt] ^ kx));
            }
            uint32_t bh[4][2], bl[4][2];
            #pragma unroll
            for (int p = 0; p < 2; p++) {
                LDSM4(bh[2*p][0], bh[2*p][1], bh[2*p+1][0], bh[2*p+1][1], sb + 2 * MAT_B + (bOff[p] ^ kx));
                LDSM4(bl[2*p][0], bl[2*p][1], bl[2*p+1][0], bl[2*p+1][1], sb + 3 * MAT_B + (bOff[p] ^ kx));
            }
            #pragma unroll
            for (int mt = 0; mt < 4; mt++)
                #pragma unroll
                for (int nt = 0; nt < 4; nt++) {
                    MMA16816(acc[mt][nt], ah[mt], bh[nt]);
                    MMA16816(acc[mt][nt], ah[mt], bl[nt]);
                    MMA16816(acc[mt][nt], al[mt], bh[nt]);
                }
        }
        __syncthreads();
    }

    // epilogue
    const int g = lane >> 2, tg = lane & 3;
    #pragma unroll
    for (int mt = 0; mt < 4; mt++) {
        const int r = m0 + wm * 64 + mt * 16 + g;
        #pragma unroll
        for (int nt = 0; nt < 4; nt++) {
            const int col = n0 + wn * 32 + nt * 8 + 2 * tg;
            float v0 = alpha * acc[mt][nt][0];
            float v1 = alpha * acc[mt][nt][1];
            float v2 = alpha * acc[mt][nt][2];
            float v3 = alpha * acc[mt][nt][3];
            if (flags & 4) {
                bf16 h0, l0, h1, l1;
                split_bf16(v0, h0, l0); split_bf16(v1, h1, l1);
                __nv_bfloat162 hp, lp;
                hp.x = h0; hp.y = h1; lp.x = l0; lp.y = l1;
                *(__nv_bfloat162*)(Ch + (ll)bz * sC + (ll)r * ldc + col) = hp;
                *(__nv_bfloat162*)(Cl + (ll)bz * sC + (ll)r * ldc + col) = lp;
                split_bf16(v2, h0, l0); split_bf16(v3, h1, l1);
                hp.x = h0; hp.y = h1; lp.x = l0; lp.y = l1;
                *(__nv_bfloat162*)(Ch + (ll)bz * sC + (ll)(r + 8) * ldc + col) = hp;
                *(__nv_bfloat162*)(Cl + (ll)bz * sC + (ll)(r + 8) * ldc + col) = lp;
            } else {
                float2 p0, p1;
                p0.x = v0; p0.y = v1; p1.x = v2; p1.y = v3;
                *(float2*)(Cf + (ll)bz * sC + (ll)r * ldc + col) = p0;
                *(float2*)(Cf + (ll)bz * sC + (ll)(r + 8) * ldc + col) = p1;
            }
        }
    }
}

// ---------------- causal softmax: S f32 -> P hi/lo bf16 ----------------------
__global__ void softmax_kernel(const float* __restrict__ S,
                               bf16* __restrict__ Ph, bf16* __restrict__ Pl)
{
    const ll row = blockIdx.x;
    const int b = (int)(row >> 12);
    const int t = (int)(row & (T_ - 1));
    const float* p = S + ((ll)b * T_ + t) * T_;
    bf16* oh = Ph + ((ll)b * T_ + t) * T_;
    bf16* ol = Pl + ((ll)b * T_ + t) * T_;
    const int n  = t + 1;
    const int tb = ((t >> 7) + 1) << 7;   // zero-fill to 128-tile edge
    const int tid = threadIdx.x;

    __shared__ float redm[8], reds[8];

    float m = -3.402823466e38f;
    for (int i = tid; i < n; i += 256) m = fmaxf(m, p[i]);
    #pragma unroll
    for (int o = 16; o > 0; o >>= 1) m = fmaxf(m, __shfl_xor_sync(0xffffffffu, m, o));
    if ((tid & 31) == 0) redm[tid >> 5] = m;
    __syncthreads();
    m = redm[0];
    #pragma unroll
    for (int i = 1; i < 8; i++) m = fmaxf(m, redm[i]);

    float ev[16];
    float s = 0.f;
    int cnt = 0;
    for (int i = tid; i < n; i += 256) {
        float e = __expf(p[i] - m);
        ev[cnt++] = e;
        s += e;
    }
    #pragma unroll
    for (int o = 16; o > 0; o >>= 1) s += __shfl_xor_sync(0xffffffffu, s, o);
    if ((tid & 31) == 0) reds[tid >> 5] = s;
    __syncthreads();
    s = reds[0] + reds[1] + reds[2] + reds[3] + reds[4] + reds[5] + reds[6] + reds[7];
    const float inv = 1.0f / s;

    cnt = 0;
    for (int i = tid; i < n; i += 256) {
        float v = ev[cnt++] * inv;
        bf16 h, l; split_bf16(v, h, l);
        oh[i] = h; ol[i] = l;
    }
    const bf16 z = __float2bfloat16_rn(0.f);
    for (int i = n + tid; i < tb; i += 256) { oh[i] = z; ol[i] = z; }
}

// ---------------- launch ----------------------------------------------------
extern "C" void kernel_launch(void* const* d_in, const int* in_sizes, int n_in,
                              void* d_out, int out_size)
{
    const float* x     = (const float*)d_in[0];
    const float* gamma = (const float*)d_in[2];
    const float* beta  = (const float*)d_in[3];
    const float* Wqkv  = (const float*)d_in[4];
    const float* Wproj = (const float*)d_in[5];
    float* out = (float*)d_out;

    bf16 *xnh, *xnl, *wqh, *wql, *wph, *wpl, *qh, *ql, *vth, *vtl, *pph, *ppl, *ath, *atl;
    float* S;
    cudaGetSymbolAddress((void**)&xnh, g_xn_h);    cudaGetSymbolAddress((void**)&xnl, g_xn_l);
    cudaGetSymbolAddress((void**)&wqh, g_wqkvT_h); cudaGetSymbolAddress((void**)&wql, g_wqkvT_l);
    cudaGetSymbolAddress((void**)&wph, g_wprojT_h); cudaGetSymbolAddress((void**)&wpl, g_wprojT_l);
    cudaGetSymbolAddress((void**)&qh,  g_qkv_h);   cudaGetSymbolAddress((void**)&ql,  g_qkv_l);
    cudaGetSymbolAddress((void**)&vth, g_vt_h);    cudaGetSymbolAddress((void**)&vtl, g_vt_l);
    cudaGetSymbolAddress((void**)&S,   g_S);
    cudaGetSymbolAddress((void**)&pph, g_P_h);     cudaGetSymbolAddress((void**)&ppl, g_P_l);
    cudaGetSymbolAddress((void**)&ath, g_att_h);   cudaGetSymbolAddress((void**)&atl, g_att_l);

    cudaFuncSetAttribute(gemm_mma, cudaFuncAttributeMaxDynamicSharedMemorySize, GSMEM);

    // 1. LN -> hi/lo
    ln_kernel<<<BT_, 128>>>(x, gamma, beta, xnh, xnl);

    // 2. weight transposes (independent)
    wtrans_kernel<<<dim3(N3_ / 32, D_ / 32), dim3(32, 8)>>>(Wqkv, D_, N3_, wqh, wql);
    wtrans_kernel<<<dim3(D_ / 32, D_ / 32), dim3(32, 8)>>>(Wproj, D_, D_, wph, wpl);

    // 3. QKV: xn @ WqkvT^T -> qkv hi/lo  [16384,1536]
    gemm_mma<<<dim3(N3_ / 128, BT_ / 128, 1), 256, GSMEM>>>(
        xnh, xnl, D_, 0, wqh, wql, D_, 0,
        nullptr, qh, ql, N3_, 0, D_, 1.0f, /*flags=*/4);

    // 4. V transpose per batch
    vtrans_kernel<<<dim3(T_ / 32, D_ / 32, B_), dim3(32, 8)>>>(qh, ql, vth, vtl);

    // 5. scores: Q @ K^T * scale -> S f32 (causal tile skip)
    gemm_mma<<<dim3(T_ / 128, T_ / 128, B_), 256, GSMEM>>>(
        qh + 0,  ql + 0,  N3_, (ll)T_ * N3_,
        qh + D_, ql + D_, N3_, (ll)T_ * N3_,
        S, nullptr, nullptr, T_, (ll)T_ * T_, D_, SCALE_QK, /*flags=*/1);

    // 6. softmax -> P hi/lo (zero-fill to tile edge)
    softmax_kernel<<<BT_, 256>>>(S, pph, ppl);

    // 7. PV: P @ VT^T -> att hi/lo (causal kbound)
    gemm_mma<<<dim3(D_ / 128, T_ / 128, B_), 256, GSMEM>>>(
        pph, ppl, T_, (ll)T_ * T_,
        vth, vtl, T_, (ll)D_ * T_,
        nullptr, ath, atl, D_, (ll)T_ * D_, T_, 1.0f, /*flags=*/2 | 4);

    // 8. projection: att @ WprojT^T -> out f32
    gemm_mma<<<dim3(D_ / 128, BT_ / 128, 1), 256, GSMEM>>>(
        ath, atl, D_, 0, wph, wpl, D_, 0,
        out, nullptr, nullptr, D_, 0, D_, 1.0f, /*flags=*/0);
}

// round 9
// speedup vs baseline: 2.5295x; 1.1164x over previous
#include <cuda_runtime.h>
#include <cuda_bf16.h>
#include <cstdint>
#include <math.h>

// Problem constants
#define B_  4
#define T_  4096
#define D_  512
#define BT_ (B_ * T_)          // 16384
#define N3_ (3 * D_)           // 1536
#define EPS_LN 1e-5f
#define SCALE_QK 0.04419417382415922f   // 1/sqrt(512)

typedef long long ll;
typedef __nv_bfloat16 bf16;

// ---------------- scratch (device globals) ----------------------------------
__device__ bf16  g_xn_h [(ll)BT_ * D_];
__device__ bf16  g_xn_l [(ll)BT_ * D_];
__device__ bf16  g_wqkvT_h [(ll)N3_ * D_];
__device__ bf16  g_wqkvT_l [(ll)N3_ * D_];
__device__ bf16  g_wprojT_h[(ll)D_ * D_];
__device__ bf16  g_wprojT_l[(ll)D_ * D_];
__device__ bf16  g_qkv_h[(ll)BT_ * N3_];
__device__ bf16  g_qkv_l[(ll)BT_ * N3_];
__device__ bf16  g_vt_h [(ll)B_ * D_ * T_];
__device__ bf16  g_vt_l [(ll)B_ * D_ * T_];
__device__ float g_S    [(ll)B_ * T_ * T_];
__device__ bf16  g_P_h  [(ll)B_ * T_ * T_];
__device__ bf16  g_P_l  [(ll)B_ * T_ * T_];
__device__ bf16  g_att_h[(ll)BT_ * D_];
__device__ bf16  g_att_l[(ll)BT_ * D_];

// ---------------- PTX helpers (all base sm_103-safe) -------------------------
__device__ __forceinline__ uint32_t smem_u32(const void* p) {
    uint32_t a;
    asm("{ .reg .u64 t; cvta.to.shared.u64 t, %1; cvt.u32.u64 %0, t; }" : "=r"(a) : "l"(p));
    return a;
}
__device__ __forceinline__ void cp16(uint32_t d, const void* g) {
    asm volatile("cp.async.cg.shared.global [%0], [%1], 16;" :: "r"(d), "l"(g) : "memory");
}
#define CP_COMMIT() asm volatile("cp.async.commit_group;" ::: "memory")
#define CP_WAIT(n)  asm volatile("cp.async.wait_group %0;" :: "n"(n) : "memory")

#define LDSM4(r0, r1, r2, r3, a) \
    asm volatile("ldmatrix.sync.aligned.m8n8.x4.shared.b16 {%0,%1,%2,%3}, [%4];" \
        : "=r"(r0), "=r"(r1), "=r"(r2), "=r"(r3) : "r"(a))

#define MMA16816(d, a, b) \
    asm volatile("mma.sync.aligned.m16n8k16.row.col.f32.bf16.bf16.f32 " \
        "{%0,%1,%2,%3}, {%4,%5,%6,%7}, {%8,%9}, {%0,%1,%2,%3};" \
        : "+f"((d)[0]), "+f"((d)[1]), "+f"((d)[2]), "+f"((d)[3]) \
        : "r"((a)[0]), "r"((a)[1]), "r"((a)[2]), "r"((a)[3]), "r"((b)[0]), "r"((b)[1]))

__device__ __forceinline__ void split_bf16(float v, bf16& h, bf16& l) {
    h = __float2bfloat16_rn(v);
    l = __float2bfloat16_rn(v - __bfloat162float(h));
}

// ---------------- LayerNorm -> hi/lo bf16 ------------------------------------
__global__ void ln_kernel(const float* __restrict__ x,
                          const float* __restrict__ gamma,
                          const float* __restrict__ beta,
                          bf16* __restrict__ xh, bf16* __restrict__ xl)
{
    const ll row = blockIdx.x;
    const int tid = threadIdx.x;             // 0..127
    float4 v = ((const float4*)(x + row * D_))[tid];

    float s  = v.x + v.y + v.z + v.w;
    float ss = v.x*v.x + v.y*v.y + v.z*v.z + v.w*v.w;
    #pragma unroll
    for (int o = 16; o > 0; o >>= 1) {
        s  += __shfl_xor_sync(0xffffffffu, s,  o);
        ss += __shfl_xor_sync(0xffffffffu, ss, o);
    }
    __shared__ float rs[4], rss[4];
    if ((tid & 31) == 0) { rs[tid >> 5] = s; rss[tid >> 5] = ss; }
    __syncthreads();
    s  = rs[0] + rs[1] + rs[2] + rs[3];
    ss = rss[0] + rss[1] + rss[2] + rss[3];

    const float mu   = s * (1.0f / D_);
    const float var  = ss * (1.0f / D_) - mu * mu;
    const float rstd = rsqrtf(var + EPS_LN);

    float4 g = ((const float4*)gamma)[tid];
    float4 b = ((const float4*)beta)[tid];
    float o0 = (v.x - mu) * rstd * g.x + b.x;
    float o1 = (v.y - mu) * rstd * g.y + b.y;
    float o2 = (v.z - mu) * rstd * g.z + b.z;
    float o3 = (v.w - mu) * rstd * g.w + b.w;

    bf16 h[4], l[4];
    split_bf16(o0, h[0], l[0]); split_bf16(o1, h[1], l[1]);
    split_bf16(o2, h[2], l[2]); split_bf16(o3, h[3], l[3]);
    *(ulonglong1*)(xh + row * D_ + tid * 4) = *(ulonglong1*)h;
    *(ulonglong1*)(xl + row * D_ + tid * 4) = *(ulonglong1*)l;
}

// ---------------- weight transpose-convert: W[K,N] f32 -> Wt[N,K] hi/lo ------
__global__ void wtrans_kernel(const float* __restrict__ W, int K, int N,
                              bf16* __restrict__ Th, bf16* __restrict__ Tl)
{
    __shared__ float t[32][33];
    const int n0 = blockIdx.x * 32, k0 = blockIdx.y * 32;
    const int tx = threadIdx.x, ty = threadIdx.y;
    #pragma unroll
    for (int i = 0; i < 32; i += 8)
        t[ty + i][tx] = W[(ll)(k0 + ty + i) * N + n0 + tx];
    __syncthreads();
    #pragma unroll
    for (int i = 0; i < 32; i += 8) {
        float v = t[tx][ty + i];
        bf16 h, l; split_bf16(v, h, l);
        Th[(ll)(n0 + ty + i) * K + k0 + tx] = h;
        Tl[(ll)(n0 + ty + i) * K + k0 + tx] = l;
    }
}

// ---------------- V transpose: qkv hi/lo [BT,1536] -> VT hi/lo [B,512,T] -----
__global__ void vtrans_kernel(const bf16* __restrict__ qh, const bf16* __restrict__ ql,
                              bf16* __restrict__ vh, bf16* __restrict__ vl)
{
    __shared__ bf16 th[32][33], tl[32][33];
    const int s0 = blockIdx.x * 32, c0 = blockIdx.y * 32, b = blockIdx.z;
    const int tx = threadIdx.x, ty = threadIdx.y;
    const ll qb = ((ll)b * T_) * N3_ + 2 * D_;
    #pragma unroll
    for (int i = 0; i < 32; i += 8) {
        th[ty + i][tx] = qh[qb + (ll)(s0 + ty + i) * N3_ + c0 + tx];
        tl[ty + i][tx] = ql[qb + (ll)(s0 + ty + i) * N3_ + c0 + tx];
    }
    __syncthreads();
    const ll vb = (ll)b * D_ * T_;
    #pragma unroll
    for (int i = 0; i < 32; i += 8) {
        vh[vb + (ll)(c0 + ty + i) * T_ + s0 + tx] = th[tx][ty + i];
        vl[vb + (ll)(c0 + ty + i) * T_ + s0 + tx] = tl[tx][ty + i];
    }
}

// ---------------- bf16x3 NT GEMM on mma.sync (HMMA) --------------------------
// C[M,N] = alpha * (Ah+Al)[M,K] @ (Bh+Bl)[N,K]^T
// flags: 1 = causal tile skip (bx>by), 2 = causal kbound, 4 = bf16 hi/lo output
// Tile: CTA 128x128, BK=32, 8 warps (2x4), warp tile 64x32, 4x4 m16n8k16.
// 2 CTAs/SM (128-reg cap) for latency hiding.
#define MAT_B 8192                // 128 rows * 32 k * 2B
#define STG_B (4 * MAT_B)         // Ah, Al, Bh, Bl
#define GSMEM (2 * STG_B)         // 64 KB, double buffered

__global__ __launch_bounds__(256, 2)
void gemm_mma(const bf16* __restrict__ Ah, const bf16* __restrict__ Al, int lda, ll sA,
              const bf16* __restrict__ Bh, const bf16* __restrict__ Bl, int ldb, ll sB,
              float* __restrict__ Cf, bf16* __restrict__ Ch, bf16* __restrict__ Cl,
              int ldc, ll sC, int K, float alpha, int flags)
{
    const int bx = blockIdx.x, by = blockIdx.y, bz = blockIdx.z;
    if ((flags & 1) && bx > by) return;

    extern __shared__ char smem[];
    const uint32_t sbase = smem_u32(smem);
    const int tid = threadIdx.x;
    const int wid = tid >> 5, lane = tid & 31;
    const int wm = wid >> 2, wn = wid & 3;

    const int m0 = by * 128, n0 = bx * 128;
    int Keff = K;
    if (flags & 2) { int kb = m0 + 128; Keff = kb < K ? kb : K; }
    const int NK = Keff / 32;

    const char* srcAh = (const char*)(Ah + (ll)bz * sA + (ll)m0 * lda);
    const char* srcAl = (const char*)(Al + (ll)bz * sA + (ll)m0 * lda);
    const char* srcBh = (const char*)(Bh + (ll)bz * sB + (ll)n0 * ldb);
    const char* srcBl = (const char*)(Bl + (ll)bz * sB + (ll)n0 * ldb);
    const ll strA = (ll)lda * 2, strB = (ll)ldb * 2;

    // loader: 512 16B chunks per matrix per stage; thread does 2 chunks/matrix
    const int cid0 = tid * 2;
    const int lrow0 = cid0 >> 2, lc0 = cid0 & 3;
    const int lrow1 = (cid0 + 1) >> 2, lc1 = (cid0 + 1) & 3;
    const uint32_t ldoff0 = lrow0 * 64 + (lc0 ^ ((lrow0 >> 1) & 3)) * 16;
    const uint32_t ldoff1 = lrow1 * 64 + (lc1 ^ ((lrow1 >> 1) & 3)) * 16;

    auto load_stage = [&](int s, int k0) {
        const uint32_t db = sbase + s * STG_B;
        const ll ko = (ll)k0 * 2;
        const ll gA0 = (ll)lrow0 * strA + ko + lc0 * 16;
        const ll gA1 = (ll)lrow1 * strA + ko + lc1 * 16;
        const ll gB0 = (ll)lrow0 * strB + ko + lc0 * 16;
        const ll gB1 = (ll)lrow1 * strB + ko + lc1 * 16;
        cp16(db + 0 * MAT_B + ldoff0, srcAh + gA0);
        cp16(db + 0 * MAT_B + ldoff1, srcAh + gA1);
        cp16(db + 1 * MAT_B + ldoff0, srcAl + gA0);
        cp16(db + 1 * MAT_B + ldoff1, srcAl + gA1);
        cp16(db + 2 * MAT_B + ldoff0, srcBh + gB0);
        cp16(db + 2 * MAT_B + ldoff1, srcBh + gB1);
        cp16(db + 3 * MAT_B + ldoff0, srcBl + gB0);
        cp16(db + 3 * MAT_B + ldoff1, srcBl + gB1);
    };

    // ldmatrix per-thread offsets within a matrix region (for ks=0; ^32 for ks=1)
    uint32_t aOff[4], bOff[2];
    {
        const int l15 = lane & 15, l4 = lane >> 4;
        #pragma unroll
        for (int mt = 0; mt < 4; mt++) {
            int r = wm * 64 + mt * 16 + l15;
            aOff[mt] = r * 64 + ((l4 ^ ((r >> 1) & 3)) * 16);
        }
        const int l7 = lane & 7, l3 = (lane >> 3) & 1;
        #pragma unroll
        for (int p = 0; p < 2; p++) {
            int r = wn * 32 + (p * 2 + l4) * 8 + l7;
            bOff[p] = r * 64 + ((l3 ^ ((r >> 1) & 3)) * 16);
        }
    }

    float acc[4][4][4] = {};

    load_stage(0, 0);
    CP_COMMIT();

    for (int c = 0; c < NK; ++c) {
        const int s = c & 1;
        if (c + 1 < NK) {
            load_stage((c + 1) & 1, (c + 1) * 32);
            CP_COMMIT();
            CP_WAIT(1);
        } else {
            CP_WAIT(0);
        }
        __syncthreads();

        const uint32_t sb = sbase + s * STG_B;
        #pragma unroll
        for (int ks = 0; ks < 2; ks++) {
            const uint32_t kx = ks * 32;
            // B fragments first (16 regs live)
            uint32_t bh[4][2], bl[4][2];
            #pragma unroll
            for (int p = 0; p < 2; p++) {
                LDSM4(bh[2*p][0], bh[2*p][1], bh[2*p+1][0], bh[2*p+1][1], sb + 2 * MAT_B + (bOff[p] ^ kx));
                LDSM4(bl[2*p][0], bl[2*p][1], bl[2*p+1][0], bl[2*p+1][1], sb + 3 * MAT_B + (bOff[p] ^ kx));
            }
            // stream A fragments per mt (8 regs live at a time)
            #pragma unroll
            for (int mt = 0; mt < 4; mt++) {
                uint32_t ah[4], al[4];
                LDSM4(ah[0], ah[1], ah[2], ah[3], sb + 0 * MAT_B + (aOff[mt] ^ kx));
                LDSM4(al[0], al[1], al[2], al[3], sb + 1 * MAT_B + (aOff[mt] ^ kx));
                #pragma unroll
                for (int nt = 0; nt < 4; nt++) {
                    MMA16816(acc[mt][nt], ah, bh[nt]);
                    MMA16816(acc[mt][nt], ah, bl[nt]);
                    MMA16816(acc[mt][nt], al, bh[nt]);
                }
            }
        }
        __syncthreads();
    }

    // epilogue
    const int g = lane >> 2, tg = lane & 3;
    #pragma unroll
    for (int mt = 0; mt < 4; mt++) {
        const int r = m0 + wm * 64 + mt * 16 + g;
        #pragma unroll
        for (int nt = 0; nt < 4; nt++) {
            const int col = n0 + wn * 32 + nt * 8 + 2 * tg;
            float v0 = alpha * acc[mt][nt][0];
            float v1 = alpha * acc[mt][nt][1];
            float v2 = alpha * acc[mt][nt][2];
            float v3 = alpha * acc[mt][nt][3];
            if (flags & 4) {
                bf16 h0, l0, h1, l1;
                split_bf16(v0, h0, l0); split_bf16(v1, h1, l1);
                __nv_bfloat162 hp, lp;
                hp.x = h0; hp.y = h1; lp.x = l0; lp.y = l1;
                *(__nv_bfloat162*)(Ch + (ll)bz * sC + (ll)r * ldc + col) = hp;
                *(__nv_bfloat162*)(Cl + (ll)bz * sC + (ll)r * ldc + col) = lp;
                split_bf16(v2, h0, l0); split_bf16(v3, h1, l1);
                hp.x = h0; hp.y = h1; lp.x = l0; lp.y = l1;
                *(__nv_bfloat162*)(Ch + (ll)bz * sC + (ll)(r + 8) * ldc + col) = hp;
                *(__nv_bfloat162*)(Cl + (ll)bz * sC + (ll)(r + 8) * ldc + col) = lp;
            } else {
                float2 p0, p1;
                p0.x = v0; p0.y = v1; p1.x = v2; p1.y = v3;
                *(float2*)(Cf + (ll)bz * sC + (ll)r * ldc + col) = p0;
                *(float2*)(Cf + (ll)bz * sC + (ll)(r + 8) * ldc + col) = p1;
            }
        }
    }
}

// ---------------- causal softmax: S f32 -> P hi/lo bf16 ----------------------
__global__ void softmax_kernel(const float* __restrict__ S,
                               bf16* __restrict__ Ph, bf16* __restrict__ Pl)
{
    const ll row = blockIdx.x;
    const int b = (int)(row >> 12);
    const int t = (int)(row & (T_ - 1));
    const float* p = S + ((ll)b * T_ + t) * T_;
    bf16* oh = Ph + ((ll)b * T_ + t) * T_;
    bf16* ol = Pl + ((ll)b * T_ + t) * T_;
    const int n  = t + 1;
    const int tb = ((t >> 7) + 1) << 7;   // zero-fill to 128-tile edge
    const int tid = threadIdx.x;

    __shared__ float redm[8], reds[8];

    float m = -3.402823466e38f;
    for (int i = tid; i < n; i += 256) m = fmaxf(m, p[i]);
    #pragma unroll
    for (int o = 16; o > 0; o >>= 1) m = fmaxf(m, __shfl_xor_sync(0xffffffffu, m, o));
    if ((tid & 31) == 0) redm[tid >> 5] = m;
    __syncthreads();
    m = redm[0];
    #pragma unroll
    for (int i = 1; i < 8; i++) m = fmaxf(m, redm[i]);

    float ev[16];
    float s = 0.f;
    int cnt = 0;
    for (int i = tid; i < n; i += 256) {
        float e = __expf(p[i] - m);
        ev[cnt++] = e;
        s += e;
    }
    #pragma unroll
    for (int o = 16; o > 0; o >>= 1) s += __shfl_xor_sync(0xffffffffu, s, o);
    if ((tid & 31) == 0) reds[tid >> 5] = s;
    __syncthreads();
    s = reds[0] + reds[1] + reds[2] + reds[3] + reds[4] + reds[5] + reds[6] + reds[7];
    const float inv = 1.0f / s;

    cnt = 0;
    for (int i = tid; i < n; i += 256) {
        float v = ev[cnt++] * inv;
        bf16 h, l; split_bf16(v, h, l);
        oh[i] = h; ol[i] = l;
    }
    const bf16 z = __float2bfloat16_rn(0.f);
    for (int i = n + tid; i < tb; i += 256) { oh[i] = z; ol[i] = z; }
}

// ---------------- launch ----------------------------------------------------
extern "C" void kernel_launch(void* const* d_in, const int* in_sizes, int n_in,
                              void* d_out, int out_size)
{
    const float* x     = (const float*)d_in[0];
    const float* gamma = (const float*)d_in[2];
    const float* beta  = (const float*)d_in[3];
    const float* Wqkv  = (const float*)d_in[4];
    const float* Wproj = (const float*)d_in[5];
    float* out = (float*)d_out;

    bf16 *xnh, *xnl, *wqh, *wql, *wph, *wpl, *qh, *ql, *vth, *vtl, *pph, *ppl, *ath, *atl;
    float* S;
    cudaGetSymbolAddress((void**)&xnh, g_xn_h);    cudaGetSymbolAddress((void**)&xnl, g_xn_l);
    cudaGetSymbolAddress((void**)&wqh, g_wqkvT_h); cudaGetSymbolAddress((void**)&wql, g_wqkvT_l);
    cudaGetSymbolAddress((void**)&wph, g_wprojT_h); cudaGetSymbolAddress((void**)&wpl, g_wprojT_l);
    cudaGetSymbolAddress((void**)&qh,  g_qkv_h);   cudaGetSymbolAddress((void**)&ql,  g_qkv_l);
    cudaGetSymbolAddress((void**)&vth, g_vt_h);    cudaGetSymbolAddress((void**)&vtl, g_vt_l);
    cudaGetSymbolAddress((void**)&S,   g_S);
    cudaGetSymbolAddress((void**)&pph, g_P_h);     cudaGetSymbolAddress((void**)&ppl, g_P_l);
    cudaGetSymbolAddress((void**)&ath, g_att_h);   cudaGetSymbolAddress((void**)&atl, g_att_l);

    cudaFuncSetAttribute(gemm_mma, cudaFuncAttributeMaxDynamicSharedMemorySize, GSMEM);

    // 1. LN -> hi/lo
    ln_kernel<<<BT_, 128>>>(x, gamma, beta, xnh, xnl);

    // 2. weight transposes (independent)
    wtrans_kernel<<<dim3(N3_ / 32, D_ / 32), dim3(32, 8)>>>(Wqkv, D_, N3_, wqh, wql);
    wtrans_kernel<<<dim3(D_ / 32, D_ / 32), dim3(32, 8)>>>(Wproj, D_, D_, wph, wpl);

    // 3. QKV: xn @ WqkvT^T -> qkv hi/lo  [16384,1536]
    gemm_mma<<<dim3(N3_ / 128, BT_ / 128, 1), 256, GSMEM>>>(
        xnh, xnl, D_, 0, wqh, wql, D_, 0,
        nullptr, qh, ql, N3_, 0, D_, 1.0f, /*flags=*/4);

    // 4. V transpose per batch
    vtrans_kernel<<<dim3(T_ / 32, D_ / 32, B_), dim3(32, 8)>>>(qh, ql, vth, vtl);

    // 5. scores: Q @ K^T * scale -> S f32 (causal tile skip)
    gemm_mma<<<dim3(T_ / 128, T_ / 128, B_), 256, GSMEM>>>(
        qh + 0,  ql + 0,  N3_, (ll)T_ * N3_,
        qh + D_, ql + D_, N3_, (ll)T_ * N3_,
        S, nullptr, nullptr, T_, (ll)T_ * T_, D_, SCALE_QK, /*flags=*/1);

    // 6. softmax -> P hi/lo (zero-fill to tile edge)
    softmax_kernel<<<BT_, 256>>>(S, pph, ppl);

    // 7. PV: P @ VT^T -> att hi/lo (causal kbound)
    gemm_mma<<<dim3(D_ / 128, T_ / 128, B_), 256, GSMEM>>>(
        pph, ppl, T_, (ll)T_ * T_,
        vth, vtl, T_, (ll)D_ * T_,
        nullptr, ath, atl, D_, (ll)T_ * D_, T_, 1.0f, /*flags=*/2 | 4);

    // 8. projection: att @ WprojT^T -> out f32
    gemm_mma<<<dim3(D_ / 128, BT_ / 128, 1), 256, GSMEM>>>(
        ath, atl, D_, 0, wph, wpl, D_, 0,
        out, nullptr, nullptr, D_, 0, D_, 1.0f, /*flags=*/0);
}

// round 10
// speedup vs baseline: 2.5606x; 1.0123x over previous
#include <cuda_runtime.h>
#include <cuda_bf16.h>
#include <cstdint>
#include <math.h>

// Problem constants
#define B_  4
#define T_  4096
#define D_  512
#define BT_ (B_ * T_)          // 16384
#define N3_ (3 * D_)           // 1536
#define EPS_LN 1e-5f
#define SCALE_QK 0.04419417382415922f   // 1/sqrt(512)

typedef long long ll;
typedef __nv_bfloat16 bf16;

// ---------------- scratch (device globals) ----------------------------------
__device__ bf16  g_xn_h [(ll)BT_ * D_];
__device__ bf16  g_xn_l [(ll)BT_ * D_];
__device__ bf16  g_wqkvT_h [(ll)N3_ * D_];
__device__ bf16  g_wqkvT_l [(ll)N3_ * D_];
__device__ bf16  g_wprojT_h[(ll)D_ * D_];
__device__ bf16  g_wprojT_l[(ll)D_ * D_];
__device__ bf16  g_qkv_h[(ll)BT_ * N3_];
__device__ bf16  g_qkv_l[(ll)BT_ * N3_];
__device__ bf16  g_vt_h [(ll)B_ * D_ * T_];
__device__ bf16  g_vt_l [(ll)B_ * D_ * T_];
__device__ float g_S    [(ll)B_ * T_ * T_];
__device__ bf16  g_P_h  [(ll)B_ * T_ * T_];
__device__ bf16  g_P_l  [(ll)B_ * T_ * T_];
__device__ bf16  g_att_h[(ll)BT_ * D_];
__device__ bf16  g_att_l[(ll)BT_ * D_];

// ---------------- PTX helpers (all base sm_103-safe) -------------------------
__device__ __forceinline__ uint32_t smem_u32(const void* p) {
    uint32_t a;
    asm("{ .reg .u64 t; cvta.to.shared.u64 t, %1; cvt.u32.u64 %0, t; }" : "=r"(a) : "l"(p));
    return a;
}
__device__ __forceinline__ void cp16(uint32_t d, const void* g) {
    asm volatile("cp.async.cg.shared.global [%0], [%1], 16;" :: "r"(d), "l"(g) : "memory");
}
#define CP_COMMIT() asm volatile("cp.async.commit_group;" ::: "memory")
#define CP_WAIT(n)  asm volatile("cp.async.wait_group %0;" :: "n"(n) : "memory")

#define LDSM4(r0, r1, r2, r3, a) \
    asm volatile("ldmatrix.sync.aligned.m8n8.x4.shared.b16 {%0,%1,%2,%3}, [%4];" \
        : "=r"(r0), "=r"(r1), "=r"(r2), "=r"(r3) : "r"(a))

#define MMA16816(d, a, b) \
    asm volatile("mma.sync.aligned.m16n8k16.row.col.f32.bf16.bf16.f32 " \
        "{%0,%1,%2,%3}, {%4,%5,%6,%7}, {%8,%9}, {%0,%1,%2,%3};" \
        : "+f"((d)[0]), "+f"((d)[1]), "+f"((d)[2]), "+f"((d)[3]) \
        : "r"((a)[0]), "r"((a)[1]), "r"((a)[2]), "r"((a)[3]), "r"((b)[0]), "r"((b)[1]))

__device__ __forceinline__ void split_bf16(float v, bf16& h, bf16& l) {
    h = __float2bfloat16_rn(v);
    l = __float2bfloat16_rn(v - __bfloat162float(h));
}

// ---------------- LayerNorm -> hi/lo bf16 ------------------------------------
__global__ void ln_kernel(const float* __restrict__ x,
                          const float* __restrict__ gamma,
                          const float* __restrict__ beta,
                          bf16* __restrict__ xh, bf16* __restrict__ xl)
{
    const ll row = blockIdx.x;
    const int tid = threadIdx.x;             // 0..127
    float4 v = ((const float4*)(x + row * D_))[tid];

    float s  = v.x + v.y + v.z + v.w;
    float ss = v.x*v.x + v.y*v.y + v.z*v.z + v.w*v.w;
    #pragma unroll
    for (int o = 16; o > 0; o >>= 1) {
        s  += __shfl_xor_sync(0xffffffffu, s,  o);
        ss += __shfl_xor_sync(0xffffffffu, ss, o);
    }
    __shared__ float rs[4], rss[4];
    if ((tid & 31) == 0) { rs[tid >> 5] = s; rss[tid >> 5] = ss; }
    __syncthreads();
    s  = rs[0] + rs[1] + rs[2] + rs[3];
    ss = rss[0] + rss[1] + rss[2] + rss[3];

    const float mu   = s * (1.0f / D_);
    const float var  = ss * (1.0f / D_) - mu * mu;
    const float rstd = rsqrtf(var + EPS_LN);

    float4 g = ((const float4*)gamma)[tid];
    float4 b = ((const float4*)beta)[tid];
    float o0 = (v.x - mu) * rstd * g.x + b.x;
    float o1 = (v.y - mu) * rstd * g.y + b.y;
    float o2 = (v.z - mu) * rstd * g.z + b.z;
    float o3 = (v.w - mu) * rstd * g.w + b.w;

    bf16 h[4], l[4];
    split_bf16(o0, h[0], l[0]); split_bf16(o1, h[1], l[1]);
    split_bf16(o2, h[2], l[2]); split_bf16(o3, h[3], l[3]);
    *(ulonglong1*)(xh + row * D_ + tid * 4) = *(ulonglong1*)h;
    *(ulonglong1*)(xl + row * D_ + tid * 4) = *(ulonglong1*)l;
}

// ---------------- weight transpose-convert: W[K,N] f32 -> Wt[N,K] hi/lo ------
__global__ void wtrans_kernel(const float* __restrict__ W, int K, int N,
                              bf16* __restrict__ Th, bf16* __restrict__ Tl)
{
    __shared__ float t[32][33];
    const int n0 = blockIdx.x * 32, k0 = blockIdx.y * 32;
    const int tx = threadIdx.x, ty = threadIdx.y;
    #pragma unroll
    for (int i = 0; i < 32; i += 8)
        t[ty + i][tx] = W[(ll)(k0 + ty + i) * N + n0 + tx];
    __syncthreads();
    #pragma unroll
    for (int i = 0; i < 32; i += 8) {
        float v = t[tx][ty + i];
        bf16 h, l; split_bf16(v, h, l);
        Th[(ll)(n0 + ty + i) * K + k0 + tx] = h;
        Tl[(ll)(n0 + ty + i) * K + k0 + tx] = l;
    }
}

// ---------------- V transpose: qkv hi/lo [BT,1536] -> VT hi/lo [B,512,T] -----
__global__ void vtrans_kernel(const bf16* __restrict__ qh, const bf16* __restrict__ ql,
                              bf16* __restrict__ vh, bf16* __restrict__ vl)
{
    __shared__ bf16 th[32][33], tl[32][33];
    const int s0 = blockIdx.x * 32, c0 = blockIdx.y * 32, b = blockIdx.z;
    const int tx = threadIdx.x, ty = threadIdx.y;
    const ll qb = ((ll)b * T_) * N3_ + 2 * D_;
    #pragma unroll
    for (int i = 0; i < 32; i += 8) {
        th[ty + i][tx] = qh[qb + (ll)(s0 + ty + i) * N3_ + c0 + tx];
        tl[ty + i][tx] = ql[qb + (ll)(s0 + ty + i) * N3_ + c0 + tx];
    }
    __syncthreads();
    const ll vb = (ll)b * D_ * T_;
    #pragma unroll
    for (int i = 0; i < 32; i += 8) {
        vh[vb + (ll)(c0 + ty + i) * T_ + s0 + tx] = th[tx][ty + i];
        vl[vb + (ll)(c0 + ty + i) * T_ + s0 + tx] = tl[tx][ty + i];
    }
}

// ---------------- bf16x3 NT GEMM on mma.sync (HMMA) --------------------------
// C[M,N] = alpha * (Ah+Al)[M,K] @ (Bh+Bl)[N,K]^T
// flags: 1 = causal tile skip (bx>by), 2 = causal kbound, 4 = bf16 hi/lo output
// Tile: CTA 128x128, BK=32, 8 warps (2x4), warp tile 64x32, 4x4 m16n8k16.
// 3-stage cp.async pipeline, ONE barrier per chunk, 2 CTAs/SM.
#define MAT_B 8192                // 128 rows * 32 k * 2B
#define STG_B (4 * MAT_B)         // Ah, Al, Bh, Bl  = 32 KB
#define NSTAGE 3
#define GSMEM (NSTAGE * STG_B)    // 96 KB

__global__ __launch_bounds__(256, 2)
void gemm_mma(const bf16* __restrict__ Ah, const bf16* __restrict__ Al, int lda, ll sA,
              const bf16* __restrict__ Bh, const bf16* __restrict__ Bl, int ldb, ll sB,
              float* __restrict__ Cf, bf16* __restrict__ Ch, bf16* __restrict__ Cl,
              int ldc, ll sC, int K, float alpha, int flags)
{
    const int bx = blockIdx.x, by = blockIdx.y, bz = blockIdx.z;
    if ((flags & 1) && bx > by) return;

    extern __shared__ char smem[];
    const uint32_t sbase = smem_u32(smem);
    const int tid = threadIdx.x;
    const int wid = tid >> 5, lane = tid & 31;
    const int wm = wid >> 2, wn = wid & 3;

    const int m0 = by * 128, n0 = bx * 128;
    int Keff = K;
    if (flags & 2) { int kb = m0 + 128; Keff = kb < K ? kb : K; }
    const int NK = Keff / 32;     // >= 4 for all call sites

    const char* srcAh = (const char*)(Ah + (ll)bz * sA + (ll)m0 * lda);
    const char* srcAl = (const char*)(Al + (ll)bz * sA + (ll)m0 * lda);
    const char* srcBh = (const char*)(Bh + (ll)bz * sB + (ll)n0 * ldb);
    const char* srcBl = (const char*)(Bl + (ll)bz * sB + (ll)n0 * ldb);
    const ll strA = (ll)lda * 2, strB = (ll)ldb * 2;

    // loader: 512 16B chunks per matrix per stage; thread does 2 chunks/matrix
    const int cid0 = tid * 2;
    const int lrow0 = cid0 >> 2, lc0 = cid0 & 3;
    const int lrow1 = (cid0 + 1) >> 2, lc1 = (cid0 + 1) & 3;
    const uint32_t ldoff0 = lrow0 * 64 + (lc0 ^ ((lrow0 >> 1) & 3)) * 16;
    const uint32_t ldoff1 = lrow1 * 64 + (lc1 ^ ((lrow1 >> 1) & 3)) * 16;

    auto load_stage = [&](int s, int k0) {
        const uint32_t db = sbase + s * STG_B;
        const ll ko = (ll)k0 * 2;
        const ll gA0 = (ll)lrow0 * strA + ko + lc0 * 16;
        const ll gA1 = (ll)lrow1 * strA + ko + lc1 * 16;
        const ll gB0 = (ll)lrow0 * strB + ko + lc0 * 16;
        const ll gB1 = (ll)lrow1 * strB + ko + lc1 * 16;
        cp16(db + 0 * MAT_B + ldoff0, srcAh + gA0);
        cp16(db + 0 * MAT_B + ldoff1, srcAh + gA1);
        cp16(db + 1 * MAT_B + ldoff0, srcAl + gA0);
        cp16(db + 1 * MAT_B + ldoff1, srcAl + gA1);
        cp16(db + 2 * MAT_B + ldoff0, srcBh + gB0);
        cp16(db + 2 * MAT_B + ldoff1, srcBh + gB1);
        cp16(db + 3 * MAT_B + ldoff0, srcBl + gB0);
        cp16(db + 3 * MAT_B + ldoff1, srcBl + gB1);
    };

    // ldmatrix per-thread offsets within a matrix region (for ks=0; ^32 for ks=1)
    uint32_t aOff[4], bOff[2];
    {
        const int l15 = lane & 15, l4 = lane >> 4;
        #pragma unroll
        for (int mt = 0; mt < 4; mt++) {
            int r = wm * 64 + mt * 16 + l15;
            aOff[mt] = r * 64 + ((l4 ^ ((r >> 1) & 3)) * 16);
        }
        const int l7 = lane & 7, l3 = (lane >> 3) & 1;
        #pragma unroll
        for (int p = 0; p < 2; p++) {
            int r = wn * 32 + (p * 2 + l4) * 8 + l7;
            bOff[p] = r * 64 + ((l3 ^ ((r >> 1) & 3)) * 16);
        }
    }

    float acc[4][4][4] = {};

    load_stage(0, 0);  CP_COMMIT();
    load_stage(1, 32); CP_COMMIT();

    int stage = 0;
    for (int c = 0; c < NK; ++c) {
        if (c + 1 < NK) { CP_WAIT(1); } else { CP_WAIT(0); }
        __syncthreads();                 // all warps done with stage (c-1)%3
        if (c + 2 < NK) {                // overwrite stage (c-1)%3 — safe now
            int ns = stage + 2; if (ns >= NSTAGE) ns -= NSTAGE;
            load_stage(ns, (c + 2) * 32);
            CP_COMMIT();
        }

        const uint32_t sb = sbase + stage * STG_B;
        #pragma unroll
        for (int ks = 0; ks < 2; ks++) {
            const uint32_t kx = ks * 32;
            uint32_t bh[4][2], bl[4][2];
            #pragma unroll
            for (int p = 0; p < 2; p++) {
                LDSM4(bh[2*p][0], bh[2*p][1], bh[2*p+1][0], bh[2*p+1][1], sb + 2 * MAT_B + (bOff[p] ^ kx));
                LDSM4(bl[2*p][0], bl[2*p][1], bl[2*p+1][0], bl[2*p+1][1], sb + 3 * MAT_B + (bOff[p] ^ kx));
            }
            #pragma unroll
            for (int mt = 0; mt < 4; mt++) {
                uint32_t ah[4], al[4];
                LDSM4(ah[0], ah[1], ah[2], ah[3], sb + 0 * MAT_B + (aOff[mt] ^ kx));
                LDSM4(al[0], al[1], al[2], al[3], sb + 1 * MAT_B + (aOff[mt] ^ kx));
                #pragma unroll
                for (int nt = 0; nt < 4; nt++) {
                    MMA16816(acc[mt][nt], ah, bh[nt]);
                    MMA16816(acc[mt][nt], ah, bl[nt]);
                    MMA16816(acc[mt][nt], al, bh[nt]);
                }
            }
        }
        if (++stage >= NSTAGE) stage = 0;
    }

    // epilogue
    const int g = lane >> 2, tg = lane & 3;
    #pragma unroll
    for (int mt = 0; mt < 4; mt++) {
        const int r = m0 + wm * 64 + mt * 16 + g;
        #pragma unroll
        for (int nt = 0; nt < 4; nt++) {
            const int col = n0 + wn * 32 + nt * 8 + 2 * tg;
            float v0 = alpha * acc[mt][nt][0];
            float v1 = alpha * acc[mt][nt][1];
            float v2 = alpha * acc[mt][nt][2];
            float v3 = alpha * acc[mt][nt][3];
            if (flags & 4) {
                bf16 h0, l0, h1, l1;
                split_bf16(v0, h0, l0); split_bf16(v1, h1, l1);
                __nv_bfloat162 hp, lp;
                hp.x = h0; hp.y = h1; lp.x = l0; lp.y = l1;
                *(__nv_bfloat162*)(Ch + (ll)bz * sC + (ll)r * ldc + col) = hp;
                *(__nv_bfloat162*)(Cl + (ll)bz * sC + (ll)r * ldc + col) = lp;
                split_bf16(v2, h0, l0); split_bf16(v3, h1, l1);
                hp.x = h0; hp.y = h1; lp.x = l0; lp.y = l1;
                *(__nv_bfloat162*)(Ch + (ll)bz * sC + (ll)(r + 8) * ldc + col) = hp;
                *(__nv_bfloat162*)(Cl + (ll)bz * sC + (ll)(r + 8) * ldc + col) = lp;
            } else {
                float2 p0, p1;
                p0.x = v0; p0.y = v1; p1.x = v2; p1.y = v3;
                *(float2*)(Cf + (ll)bz * sC + (ll)r * ldc + col) = p0;
                *(float2*)(Cf + (ll)bz * sC + (ll)(r + 8) * ldc + col) = p1;
            }
        }
    }
}

// ---------------- causal softmax: S f32 -> P hi/lo bf16 (vectorized) ---------
__global__ void softmax_kernel(const float* __restrict__ S,
                               bf16* __restrict__ Ph, bf16* __restrict__ Pl)
{
    const ll row = blockIdx.x;
    const int b = (int)(row >> 12);
    const int t = (int)(row & (T_ - 1));
    const float* p = S + ((ll)b * T_ + t) * T_;
    bf16* oh = Ph + ((ll)b * T_ + t) * T_;
    bf16* ol = Pl + ((ll)b * T_ + t) * T_;
    const int n  = t + 1;                 // valid entries
    const int n4 = n >> 2;                // full float4 count
    const int tb = ((t >> 7) + 1) << 7;   // zero-fill to 128-tile edge
    const int tid = threadIdx.x;
    const float4* p4 = (const float4*)p;

    __shared__ float redm[8], reds[8];

    // 1. max (float4 main + scalar tail)
    float m = -3.402823466e38f;
    #pragma unroll
    for (int it = 0; it < 4; it++) {
        const int i = tid + it * 256;
        if (i < n4) {
            float4 v = p4[i];
            m = fmaxf(m, fmaxf(fmaxf(v.x, v.y), fmaxf(v.z, v.w)));
        }
    }
    for (int i = (n4 << 2) + tid; i < n; i += 256) m = fmaxf(m, p[i]);
    #pragma unroll
    for (int o = 16; o > 0; o >>= 1) m = fmaxf(m, __shfl_xor_sync(0xffffffffu, m, o));
    if ((tid & 31) == 0) redm[tid >> 5] = m;
    __syncthreads();
    m = redm[0];
    #pragma unroll
    for (int i = 1; i < 8; i++) m = fmaxf(m, redm[i]);

    // 2. exp + sum (exp kept in statically-indexed registers)
    float4 ev4[4];
    float et = 0.f;
    float s = 0.f;
    #pragma unroll
    for (int it = 0; it < 4; it++) {
        const int i = tid + it * 256;
        if (i < n4) {
            float4 v = p4[i];
            float4 e;
            e.x = __expf(v.x - m); e.y = __expf(v.y - m);
            e.z = __expf(v.z - m); e.w = __expf(v.w - m);
            ev4[it] = e;
            s += e.x + e.y + e.z + e.w;
        }
    }
    {
        const int i = (n4 << 2) + tid;
        if (i < n) { et = __expf(p[i] - m); s += et; }
    }
    #pragma unroll
    for (int o = 16; o > 0; o >>= 1) s += __shfl_xor_sync(0xffffffffu, s, o);
    if ((tid & 31) == 0) reds[tid >> 5] = s;
    __syncthreads();
    s = reds[0] + reds[1] + reds[2] + reds[3] + reds[4] + reds[5] + reds[6] + reds[7];
    const float inv = 1.0f / s;

    // 3. normalize + split to hi/lo bf16 (8B vector writes on the main body)
    #pragma unroll
    for (int it = 0; it < 4; it++) {
        const int i = tid + it * 256;
        if (i < n4) {
            float4 e = ev4[it];
            float v0 = e.x * inv, v1 = e.y * inv, v2 = e.z * inv, v3 = e.w * inv;
            bf16 h[4], l[4];
            split_bf16(v0, h[0], l[0]); split_bf16(v1, h[1], l[1]);
            split_bf16(v2, h[2], l[2]); split_bf16(v3, h[3], l[3]);
            *(ulonglong1*)(oh + 4 * i) = *(ulonglong1*)h;
            *(ulonglong1*)(ol + 4 * i) = *(ulonglong1*)l;
        }
    }
    {
        const int i = (n4 << 2) + tid;
        if (i < n) {
            bf16 h, l; split_bf16(et * inv, h, l);
            oh[i] = h; ol[i] = l;
        }
    }
    const bf16 z = __float2bfloat16_rn(0.f);
    for (int i = n + tid; i < tb; i += 256) { oh[i] = z; ol[i] = z; }
}

// ---------------- launch ----------------------------------------------------
extern "C" void kernel_launch(void* const* d_in, const int* in_sizes, int n_in,
                              void* d_out, int out_size)
{
    const float* x     = (const float*)d_in[0];
    const float* gamma = (const float*)d_in[2];
    const float* beta  = (const float*)d_in[3];
    const float* Wqkv  = (const float*)d_in[4];
    const float* Wproj = (const float*)d_in[5];
    float* out = (float*)d_out;

    bf16 *xnh, *xnl, *wqh, *wql, *wph, *wpl, *qh, *ql, *vth, *vtl, *pph, *ppl, *ath, *atl;
    float* S;
    cudaGetSymbolAddress((void**)&xnh, g_xn_h);    cudaGetSymbolAddress((void**)&xnl, g_xn_l);
    cudaGetSymbolAddress((void**)&wqh, g_wqkvT_h); cudaGetSymbolAddress((void**)&wql, g_wqkvT_l);
    cudaGetSymbolAddress((void**)&wph, g_wprojT_h); cudaGetSymbolAddress((void**)&wpl, g_wprojT_l);
    cudaGetSymbolAddress((void**)&qh,  g_qkv_h);   cudaGetSymbolAddress((void**)&ql,  g_qkv_l);
    cudaGetSymbolAddress((void**)&vth, g_vt_h);    cudaGetSymbolAddress((void**)&vtl, g_vt_l);
    cudaGetSymbolAddress((void**)&S,   g_S);
    cudaGetSymbolAddress((void**)&pph, g_P_h);     cudaGetSymbolAddress((void**)&ppl, g_P_l);
    cudaGetSymbolAddress((void**)&ath, g_att_h);   cudaGetSymbolAddress((void**)&atl, g_att_l);

    cudaFuncSetAttribute(gemm_mma, cudaFuncAttributeMaxDynamicSharedMemorySize, GSMEM);

    // 1. LN -> hi/lo
    ln_kernel<<<BT_, 128>>>(x, gamma, beta, xnh, xnl);

    // 2. weight transposes (independent)
    wtrans_kernel<<<dim3(N3_ / 32, D_ / 32), dim3(32, 8)>>>(Wqkv, D_, N3_, wqh, wql);
    wtrans_kernel<<<dim3(D_ / 32, D_ / 32), dim3(32, 8)>>>(Wproj, D_, D_, wph, wpl);

    // 3. QKV: xn @ WqkvT^T -> qkv hi/lo  [16384,1536]
    gemm_mma<<<dim3(N3_ / 128, BT_ / 128, 1), 256, GSMEM>>>(
        xnh, xnl, D_, 0, wqh, wql, D_, 0,
        nullptr, qh, ql, N3_, 0, D_, 1.0f, /*flags=*/4);

    // 4. V transpose per batch
    vtrans_kernel<<<dim3(T_ / 32, D_ / 32, B_), dim3(32, 8)>>>(qh, ql, vth, vtl);

    // 5. scores: Q @ K^T * scale -> S f32 (causal tile skip)
    gemm_mma<<<dim3(T_ / 128, T_ / 128, B_), 256, GSMEM>>>(
        qh + 0,  ql + 0,  N3_, (ll)T_ * N3_,
        qh + D_, ql + D_, N3_, (ll)T_ * N3_,
        S, nullptr, nullptr, T_, (ll)T_ * T_, D_, SCALE_QK, /*flags=*/1);

    // 6. softmax -> P hi/lo (zero-fill to tile edge)
    softmax_kernel<<<BT_, 256>>>(S, pph, ppl);

    // 7. PV: P @ VT^T -> att hi/lo (causal kbound)
    gemm_mma<<<dim3(D_ / 128, T_ / 128, B_), 256, GSMEM>>>(
        pph, ppl, T_, (ll)T_ * T_,
        vth, vtl, T_, (ll)D_ * T_,
        nullptr, ath, atl, D_, (ll)T_ * D_, T_, 1.0f, /*flags=*/2 | 4);

    // 8. projection: att @ WprojT^T -> out f32
    gemm_mma<<<dim3(D_ / 128, BT_ / 128, 1), 256, GSMEM>>>(
        ath, atl, D_, 0, wph, wpl, D_, 0,
        out, nullptr, nullptr, D_, 0, D_, 1.0f, /*flags=*/0);
}

// round 11
// speedup vs baseline: 4.3098x; 1.6831x over previous
#include <cuda_runtime.h>
#include <cuda_bf16.h>
#include <cuda_fp16.h>
#include <cstdint>
#include <math.h>

// Problem constants
#define B_  4
#define T_  4096
#define D_  512
#define BT_ (B_ * T_)          // 16384
#define N3_ (3 * D_)           // 1536
#define EPS_LN 1e-5f
#define SCALE_QK 0.04419417382415922f   // 1/sqrt(512)

typedef long long ll;
typedef __nv_bfloat16 bf16;
typedef __half fp16;

// ---------------- scratch (device globals) ----------------------------------
__device__ bf16  g_xn_h [(ll)BT_ * D_];
__device__ bf16  g_xn_l [(ll)BT_ * D_];
__device__ bf16  g_wqkvT_h [(ll)N3_ * D_];
__device__ bf16  g_wqkvT_l [(ll)N3_ * D_];
__device__ bf16  g_wprojT_h[(ll)D_ * D_];
__device__ bf16  g_wprojT_l[(ll)D_ * D_];
__device__ fp16  g_qkv16[(ll)BT_ * N3_];      // Q,K,V fp16 single
__device__ fp16  g_vt16 [(ll)B_ * D_ * T_];   // V transposed fp16
__device__ float g_S    [(ll)B_ * T_ * T_];
__device__ fp16  g_P16  [(ll)B_ * T_ * T_];   // probs fp16 single
__device__ bf16  g_att_h[(ll)BT_ * D_];
__device__ bf16  g_att_l[(ll)BT_ * D_];

// ---------------- PTX helpers (all base sm_103-safe) -------------------------
__device__ __forceinline__ uint32_t smem_u32(const void* p) {
    uint32_t a;
    asm("{ .reg .u64 t; cvta.to.shared.u64 t, %1; cvt.u32.u64 %0, t; }" : "=r"(a) : "l"(p));
    return a;
}
__device__ __forceinline__ void cp16(uint32_t d, const void* g) {
    asm volatile("cp.async.cg.shared.global [%0], [%1], 16;" :: "r"(d), "l"(g) : "memory");
}
#define CP_COMMIT() asm volatile("cp.async.commit_group;" ::: "memory")
#define CP_WAIT(n)  asm volatile("cp.async.wait_group %0;" :: "n"(n) : "memory")

#define LDSM4(r0, r1, r2, r3, a) \
    asm volatile("ldmatrix.sync.aligned.m8n8.x4.shared.b16 {%0,%1,%2,%3}, [%4];" \
        : "=r"(r0), "=r"(r1), "=r"(r2), "=r"(r3) : "r"(a))

#define MMA16816(d, a, b) \
    asm volatile("mma.sync.aligned.m16n8k16.row.col.f32.bf16.bf16.f32 " \
        "{%0,%1,%2,%3}, {%4,%5,%6,%7}, {%8,%9}, {%0,%1,%2,%3};" \
        : "+f"((d)[0]), "+f"((d)[1]), "+f"((d)[2]), "+f"((d)[3]) \
        : "r"((a)[0]), "r"((a)[1]), "r"((a)[2]), "r"((a)[3]), "r"((b)[0]), "r"((b)[1]))

#define MMA16816H(d, a, b) \
    asm volatile("mma.sync.aligned.m16n8k16.row.col.f32.f16.f16.f32 " \
        "{%0,%1,%2,%3}, {%4,%5,%6,%7}, {%8,%9}, {%0,%1,%2,%3};" \
        : "+f"((d)[0]), "+f"((d)[1]), "+f"((d)[2]), "+f"((d)[3]) \
        : "r"((a)[0]), "r"((a)[1]), "r"((a)[2]), "r"((a)[3]), "r"((b)[0]), "r"((b)[1]))

__device__ __forceinline__ void split_bf16(float v, bf16& h, bf16& l) {
    h = __float2bfloat16_rn(v);
    l = __float2bfloat16_rn(v - __bfloat162float(h));
}

// ---------------- LayerNorm -> hi/lo bf16 ------------------------------------
__global__ void ln_kernel(const float* __restrict__ x,
                          const float* __restrict__ gamma,
                          const float* __restrict__ beta,
                          bf16* __restrict__ xh, bf16* __restrict__ xl)
{
    const ll row = blockIdx.x;
    const int tid = threadIdx.x;             // 0..127
    float4 v = ((const float4*)(x + row * D_))[tid];

    float s  = v.x + v.y + v.z + v.w;
    float ss = v.x*v.x + v.y*v.y + v.z*v.z + v.w*v.w;
    #pragma unroll
    for (int o = 16; o > 0; o >>= 1) {
        s  += __shfl_xor_sync(0xffffffffu, s,  o);
        ss += __shfl_xor_sync(0xffffffffu, ss, o);
    }
    __shared__ float rs[4], rss[4];
    if ((tid & 31) == 0) { rs[tid >> 5] = s; rss[tid >> 5] = ss; }
    __syncthreads();
    s  = rs[0] + rs[1] + rs[2] + rs[3];
    ss = rss[0] + rss[1] + rss[2] + rss[3];

    const float mu   = s * (1.0f / D_);
    const float var  = ss * (1.0f / D_) - mu * mu;
    const float rstd = rsqrtf(var + EPS_LN);

    float4 g = ((const float4*)gamma)[tid];
    float4 b = ((const float4*)beta)[tid];
    float o0 = (v.x - mu) * rstd * g.x + b.x;
    float o1 = (v.y - mu) * rstd * g.y + b.y;
    float o2 = (v.z - mu) * rstd * g.z + b.z;
    float o3 = (v.w - mu) * rstd * g.w + b.w;

    bf16 h[4], l[4];
    split_bf16(o0, h[0], l[0]); split_bf16(o1, h[1], l[1]);
    split_bf16(o2, h[2], l[2]); split_bf16(o3, h[3], l[3]);
    *(ulonglong1*)(xh + row * D_ + tid * 4) = *(ulonglong1*)h;
    *(ulonglong1*)(xl + row * D_ + tid * 4) = *(ulonglong1*)l;
}

// ---------------- weight transpose-convert: W[K,N] f32 -> Wt[N,K] hi/lo ------
__global__ void wtrans_kernel(const float* __restrict__ W, int K, int N,
                              bf16* __restrict__ Th, bf16* __restrict__ Tl)
{
    __shared__ float t[32][33];
    const int n0 = blockIdx.x * 32, k0 = blockIdx.y * 32;
    const int tx = threadIdx.x, ty = threadIdx.y;
    #pragma unroll
    for (int i = 0; i < 32; i += 8)
        t[ty + i][tx] = W[(ll)(k0 + ty + i) * N + n0 + tx];
    __syncthreads();
    #pragma unroll
    for (int i = 0; i < 32; i += 8) {
        float v = t[tx][ty + i];
        bf16 h, l; split_bf16(v, h, l);
        Th[(ll)(n0 + ty + i) * K + k0 + tx] = h;
        Tl[(ll)(n0 + ty + i) * K + k0 + tx] = l;
    }
}

// ---------------- V transpose: qkv16 [BT,1536] -> VT fp16 [B,512,T] ----------
__global__ void vtrans_kernel(const fp16* __restrict__ q16, fp16* __restrict__ vt)
{
    __shared__ fp16 t[32][33];
    const int s0 = blockIdx.x * 32, c0 = blockIdx.y * 32, b = blockIdx.z;
    const int tx = threadIdx.x, ty = threadIdx.y;
    const ll qb = ((ll)b * T_) * N3_ + 2 * D_;
    #pragma unroll
    for (int i = 0; i < 32; i += 8)
        t[ty + i][tx] = q16[qb + (ll)(s0 + ty + i) * N3_ + c0 + tx];
    __syncthreads();
    const ll vb = (ll)b * D_ * T_;
    #pragma unroll
    for (int i = 0; i < 32; i += 8)
        vt[vb + (ll)(c0 + ty + i) * T_ + s0 + tx] = t[tx][ty + i];
}

// ---------------- shared tile geometry ---------------------------------------
#define MAT_B 8192                // 128 rows * 32 k * 2B
#define NSTAGE 3

// ---------------- bf16x3 NT GEMM (QKV, proj) ---------------------------------
// flags: 4 = bf16 hi/lo output, 8 = fp16 single output, else f32
#define STG_B (4 * MAT_B)         // Ah, Al, Bh, Bl  = 32 KB
#define GSMEM (NSTAGE * STG_B)    // 96 KB

__global__ __launch_bounds__(256, 2)
void gemm_mma(const bf16* __restrict__ Ah, const bf16* __restrict__ Al, int lda, ll sA,
              const bf16* __restrict__ Bh, const bf16* __restrict__ Bl, int ldb, ll sB,
              float* __restrict__ Cf, bf16* __restrict__ Ch, bf16* __restrict__ Cl,
              fp16* __restrict__ C16,
              int ldc, ll sC, int K, float alpha, int flags)
{
    const int bx = blockIdx.x, by = blockIdx.y, bz = blockIdx.z;

    extern __shared__ char smem[];
    const uint32_t sbase = smem_u32(smem);
    const int tid = threadIdx.x;
    const int wid = tid >> 5, lane = tid & 31;
    const int wm = wid >> 2, wn = wid & 3;

    const int m0 = by * 128, n0 = bx * 128;
    const int NK = K / 32;

    const char* srcAh = (const char*)(Ah + (ll)bz * sA + (ll)m0 * lda);
    const char* srcAl = (const char*)(Al + (ll)bz * sA + (ll)m0 * lda);
    const char* srcBh = (const char*)(Bh + (ll)bz * sB + (ll)n0 * ldb);
    const char* srcBl = (const char*)(Bl + (ll)bz * sB + (ll)n0 * ldb);
    const ll strA = (ll)lda * 2, strB = (ll)ldb * 2;

    const int cid0 = tid * 2;
    const int lrow0 = cid0 >> 2, lc0 = cid0 & 3;
    const int lrow1 = (cid0 + 1) >> 2, lc1 = (cid0 + 1) & 3;
    const uint32_t ldoff0 = lrow0 * 64 + (lc0 ^ ((lrow0 >> 1) & 3)) * 16;
    const uint32_t ldoff1 = lrow1 * 64 + (lc1 ^ ((lrow1 >> 1) & 3)) * 16;

    auto load_stage = [&](int s, int k0) {
        const uint32_t db = sbase + s * STG_B;
        const ll ko = (ll)k0 * 2;
        const ll gA0 = (ll)lrow0 * strA + ko + lc0 * 16;
        const ll gA1 = (ll)lrow1 * strA + ko + lc1 * 16;
        const ll gB0 = (ll)lrow0 * strB + ko + lc0 * 16;
        const ll gB1 = (ll)lrow1 * strB + ko + lc1 * 16;
        cp16(db + 0 * MAT_B + ldoff0, srcAh + gA0);
        cp16(db + 0 * MAT_B + ldoff1, srcAh + gA1);
        cp16(db + 1 * MAT_B + ldoff0, srcAl + gA0);
        cp16(db + 1 * MAT_B + ldoff1, srcAl + gA1);
        cp16(db + 2 * MAT_B + ldoff0, srcBh + gB0);
        cp16(db + 2 * MAT_B + ldoff1, srcBh + gB1);
        cp16(db + 3 * MAT_B + ldoff0, srcBl + gB0);
        cp16(db + 3 * MAT_B + ldoff1, srcBl + gB1);
    };

    uint32_t aOff[4], bOff[2];
    {
        const int l15 = lane & 15, l4 = lane >> 4;
        #pragma unroll
        for (int mt = 0; mt < 4; mt++) {
            int r = wm * 64 + mt * 16 + l15;
            aOff[mt] = r * 64 + ((l4 ^ ((r >> 1) & 3)) * 16);
        }
        const int l7 = lane & 7, l3 = (lane >> 3) & 1;
        #pragma unroll
        for (int p = 0; p < 2; p++) {
            int r = wn * 32 + (p * 2 + l4) * 8 + l7;
            bOff[p] = r * 64 + ((l3 ^ ((r >> 1) & 3)) * 16);
        }
    }

    float acc[4][4][4] = {};

    load_stage(0, 0);  CP_COMMIT();
    load_stage(1, 32); CP_COMMIT();

    int stage = 0;
    for (int c = 0; c < NK; ++c) {
        if (c + 1 < NK) { CP_WAIT(1); } else { CP_WAIT(0); }
        __syncthreads();
        if (c + 2 < NK) {
            int ns = stage + 2; if (ns >= NSTAGE) ns -= NSTAGE;
            load_stage(ns, (c + 2) * 32);
            CP_COMMIT();
        }

        const uint32_t sb = sbase + stage * STG_B;
        #pragma unroll
        for (int ks = 0; ks < 2; ks++) {
            const uint32_t kx = ks * 32;
            uint32_t bh[4][2], bl[4][2];
            #pragma unroll
            for (int p = 0; p < 2; p++) {
                LDSM4(bh[2*p][0], bh[2*p][1], bh[2*p+1][0], bh[2*p+1][1], sb + 2 * MAT_B + (bOff[p] ^ kx));
                LDSM4(bl[2*p][0], bl[2*p][1], bl[2*p+1][0], bl[2*p+1][1], sb + 3 * MAT_B + (bOff[p] ^ kx));
            }
            #pragma unroll
            for (int mt = 0; mt < 4; mt++) {
                uint32_t ah[4], al[4];
                LDSM4(ah[0], ah[1], ah[2], ah[3], sb + 0 * MAT_B + (aOff[mt] ^ kx));
                LDSM4(al[0], al[1], al[2], al[3], sb + 1 * MAT_B + (aOff[mt] ^ kx));
                #pragma unroll
                for (int nt = 0; nt < 4; nt++) {
                    MMA16816(acc[mt][nt], ah, bh[nt]);
                    MMA16816(acc[mt][nt], ah, bl[nt]);
                    MMA16816(acc[mt][nt], al, bh[nt]);
                }
            }
        }
        if (++stage >= NSTAGE) stage = 0;
    }

    // epilogue
    const int g = lane >> 2, tg = lane & 3;
    #pragma unroll
    for (int mt = 0; mt < 4; mt++) {
        const int r = m0 + wm * 64 + mt * 16 + g;
        #pragma unroll
        for (int nt = 0; nt < 4; nt++) {
            const int col = n0 + wn * 32 + nt * 8 + 2 * tg;
            float v0 = alpha * acc[mt][nt][0];
            float v1 = alpha * acc[mt][nt][1];
            float v2 = alpha * acc[mt][nt][2];
            float v3 = alpha * acc[mt][nt][3];
            if (flags & 8) {
                *(__half2*)(C16 + (ll)bz * sC + (ll)r * ldc + col)       = __floats2half2_rn(v0, v1);
                *(__half2*)(C16 + (ll)bz * sC + (ll)(r + 8) * ldc + col) = __floats2half2_rn(v2, v3);
            } else if (flags & 4) {
                bf16 h0, l0, h1, l1;
                split_bf16(v0, h0, l0); split_bf16(v1, h1, l1);
                __nv_bfloat162 hp, lp;
                hp.x = h0; hp.y = h1; lp.x = l0; lp.y = l1;
                *(__nv_bfloat162*)(Ch + (ll)bz * sC + (ll)r * ldc + col) = hp;
                *(__nv_bfloat162*)(Cl + (ll)bz * sC + (ll)r * ldc + col) = lp;
                split_bf16(v2, h0, l0); split_bf16(v3, h1, l1);
                hp.x = h0; hp.y = h1; lp.x = l0; lp.y = l1;
                *(__nv_bfloat162*)(Ch + (ll)bz * sC + (ll)(r + 8) * ldc + col) = hp;
                *(__nv_bfloat162*)(Cl + (ll)bz * sC + (ll)(r + 8) * ldc + col) = lp;
            } else {
                float2 p0, p1;
                p0.x = v0; p0.y = v1; p1.x = v2; p1.y = v3;
                *(float2*)(Cf + (ll)bz * sC + (ll)r * ldc + col) = p0;
                *(float2*)(Cf + (ll)bz * sC + (ll)(r + 8) * ldc + col) = p1;
            }
        }
    }
}

// ---------------- fp16 x1 NT GEMM (scores, PV) -------------------------------
// C[M,N] = alpha * A[M,K] @ B[N,K]^T, fp16 operands, fp32 accum.
// flags: 1 = causal tile skip, 2 = causal kbound, 4 = bf16 hi/lo output
#define STG16_B (2 * MAT_B)        // A, B = 16 KB
#define GSMEM16 (NSTAGE * STG16_B) // 48 KB

__global__ __launch_bounds__(256, 2)
void gemm_mma16(const fp16* __restrict__ A, int lda, ll sA,
                const fp16* __restrict__ Bm, int ldb, ll sB,
                float* __restrict__ Cf, bf16* __restrict__ Ch, bf16* __restrict__ Cl,
                int ldc, ll sC, int K, float alpha, int flags)
{
    const int bx = blockIdx.x, by = blockIdx.y, bz = blockIdx.z;
    if ((flags & 1) && bx > by) return;

    extern __shared__ char smem[];
    const uint32_t sbase = smem_u32(smem);
    const int tid = threadIdx.x;
    const int wid = tid >> 5, lane = tid & 31;
    const int wm = wid >> 2, wn = wid & 3;

    const int m0 = by * 128, n0 = bx * 128;
    int Keff = K;
    if (flags & 2) { int kb = m0 + 128; Keff = kb < K ? kb : K; }
    const int NK = Keff / 32;     // >= 4 for all call sites

    const char* srcA = (const char*)(A  + (ll)bz * sA + (ll)m0 * lda);
    const char* srcB = (const char*)(Bm + (ll)bz * sB + (ll)n0 * ldb);
    const ll strA = (ll)lda * 2, strB = (ll)ldb * 2;

    const int cid0 = tid * 2;
    const int lrow0 = cid0 >> 2, lc0 = cid0 & 3;
    const int lrow1 = (cid0 + 1) >> 2, lc1 = (cid0 + 1) & 3;
    const uint32_t ldoff0 = lrow0 * 64 + (lc0 ^ ((lrow0 >> 1) & 3)) * 16;
    const uint32_t ldoff1 = lrow1 * 64 + (lc1 ^ ((lrow1 >> 1) & 3)) * 16;

    auto load_stage = [&](int s, int k0) {
        const uint32_t db = sbase + s * STG16_B;
        const ll ko = (ll)k0 * 2;
        cp16(db + 0 * MAT_B + ldoff0, srcA + (ll)lrow0 * strA + ko + lc0 * 16);
        cp16(db + 0 * MAT_B + ldoff1, srcA + (ll)lrow1 * strA + ko + lc1 * 16);
        cp16(db + 1 * MAT_B + ldoff0, srcB + (ll)lrow0 * strB + ko + lc0 * 16);
        cp16(db + 1 * MAT_B + ldoff1, srcB + (ll)lrow1 * strB + ko + lc1 * 16);
    };

    uint32_t aOff[4], bOff[2];
    {
        const int l15 = lane & 15, l4 = lane >> 4;
        #pragma unroll
        for (int mt = 0; mt < 4; mt++) {
            int r = wm * 64 + mt * 16 + l15;
            aOff[mt] = r * 64 + ((l4 ^ ((r >> 1) & 3)) * 16);
        }
        const int l7 = lane & 7, l3 = (lane >> 3) & 1;
        #pragma unroll
        for (int p = 0; p < 2; p++) {
            int r = wn * 32 + (p * 2 + l4) * 8 + l7;
            bOff[p] = r * 64 + ((l3 ^ ((r >> 1) & 3)) * 16);
        }
    }

    float acc[4][4][4] = {};

    load_stage(0, 0);  CP_COMMIT();
    load_stage(1, 32); CP_COMMIT();

    int stage = 0;
    for (int c = 0; c < NK; ++c) {
        if (c + 1 < NK) { CP_WAIT(1); } else { CP_WAIT(0); }
        __syncthreads();
        if (c + 2 < NK) {
            int ns = stage + 2; if (ns >= NSTAGE) ns -= NSTAGE;
            load_stage(ns, (c + 2) * 32);
            CP_COMMIT();
        }

        const uint32_t sb = sbase + stage * STG16_B;
        #pragma unroll
        for (int ks = 0; ks < 2; ks++) {
            const uint32_t kx = ks * 32;
            uint32_t bfr[4][2];
            #pragma unroll
            for (int p = 0; p < 2; p++) {
                LDSM4(bfr[2*p][0], bfr[2*p][1], bfr[2*p+1][0], bfr[2*p+1][1], sb + 1 * MAT_B + (bOff[p] ^ kx));
            }
            #pragma unroll
            for (int mt = 0; mt < 4; mt++) {
                uint32_t afr[4];
                LDSM4(afr[0], afr[1], afr[2], afr[3], sb + 0 * MAT_B + (aOff[mt] ^ kx));
                #pragma unroll
                for (int nt = 0; nt < 4; nt++)
                    MMA16816H(acc[mt][nt], afr, bfr[nt]);
            }
        }
        if (++stage >= NSTAGE) stage = 0;
    }

    // epilogue
    const int g = lane >> 2, tg = lane & 3;
    #pragma unroll
    for (int mt = 0; mt < 4; mt++) {
        const int r = m0 + wm * 64 + mt * 16 + g;
        #pragma unroll
        for (int nt = 0; nt < 4; nt++) {
            const int col = n0 + wn * 32 + nt * 8 + 2 * tg;
            float v0 = alpha * acc[mt][nt][0];
            float v1 = alpha * acc[mt][nt][1];
            float v2 = alpha * acc[mt][nt][2];
            float v3 = alpha * acc[mt][nt][3];
            if (flags & 4) {
                bf16 h0, l0, h1, l1;
                split_bf16(v0, h0, l0); split_bf16(v1, h1, l1);
                __nv_bfloat162 hp, lp;
                hp.x = h0; hp.y = h1; lp.x = l0; lp.y = l1;
                *(__nv_bfloat162*)(Ch + (ll)bz * sC + (ll)r * ldc + col) = hp;
                *(__nv_bfloat162*)(Cl + (ll)bz * sC + (ll)r * ldc + col) = lp;
                split_bf16(v2, h0, l0); split_bf16(v3, h1, l1);
                hp.x = h0; hp.y = h1; lp.x = l0; lp.y = l1;
                *(__nv_bfloat162*)(Ch + (ll)bz * sC + (ll)(r + 8) * ldc + col) = hp;
                *(__nv_bfloat162*)(Cl + (ll)bz * sC + (ll)(r + 8) * ldc + col) = lp;
            } else {
                float2 p0, p1;
                p0.x = v0; p0.y = v1; p1.x = v2; p1.y = v3;
                *(float2*)(Cf + (ll)bz * sC + (ll)r * ldc + col) = p0;
                *(float2*)(Cf + (ll)bz * sC + (ll)(r + 8) * ldc + col) = p1;
            }
        }
    }
}

// ---------------- causal softmax: S f32 -> P fp16 (vectorized) ---------------
__global__ void softmax_kernel(const float* __restrict__ S, fp16* __restrict__ P)
{
    const ll row = blockIdx.x;
    const int b = (int)(row >> 12);
    const int t = (int)(row & (T_ - 1));
    const float* p = S + ((ll)b * T_ + t) * T_;
    fp16* op = P + ((ll)b * T_ + t) * T_;
    const int n  = t + 1;                 // valid entries
    const int n4 = n >> 2;                // full float4 count
    const int tb = ((t >> 7) + 1) << 7;   // zero-fill to 128-tile edge
    const int tid = threadIdx.x;
    const float4* p4 = (const float4*)p;

    __shared__ float redm[8], reds[8];

    float m = -3.402823466e38f;
    #pragma unroll
    for (int it = 0; it < 4; it++) {
        const int i = tid + it * 256;
        if (i < n4) {
            float4 v = p4[i];
            m = fmaxf(m, fmaxf(fmaxf(v.x, v.y), fmaxf(v.z, v.w)));
        }
    }
    for (int i = (n4 << 2) + tid; i < n; i += 256) m = fmaxf(m, p[i]);
    #pragma unroll
    for (int o = 16; o > 0; o >>= 1) m = fmaxf(m, __shfl_xor_sync(0xffffffffu, m, o));
    if ((tid & 31) == 0) redm[tid >> 5] = m;
    __syncthreads();
    m = redm[0];
    #pragma unroll
    for (int i = 1; i < 8; i++) m = fmaxf(m, redm[i]);

    float4 ev4[4];
    float et = 0.f;
    float s = 0.f;
    #pragma unroll
    for (int it = 0; it < 4; it++) {
        const int i = tid + it * 256;
        if (i < n4) {
            float4 v = p4[i];
            float4 e;
            e.x = __expf(v.x - m); e.y = __expf(v.y - m);
            e.z = __expf(v.z - m); e.w = __expf(v.w - m);
            ev4[it] = e;
            s += e.x + e.y + e.z + e.w;
        }
    }
    {
        const int i = (n4 << 2) + tid;
        if (i < n) { et = __expf(p[i] - m); s += et; }
    }
    #pragma unroll
    for (int o = 16; o > 0; o >>= 1) s += __shfl_xor_sync(0xffffffffu, s, o);
    if ((tid & 31) == 0) reds[tid >> 5] = s;
    __syncthreads();
    s = reds[0] + reds[1] + reds[2] + reds[3] + reds[4] + reds[5] + reds[6] + reds[7];
    const float inv = 1.0f / s;

    #pragma unroll
    for (int it = 0; it < 4; it++) {
        const int i = tid + it * 256;
        if (i < n4) {
            float4 e = ev4[it];
            __half2 h2[2];
            h2[0] = __floats2half2_rn(e.x * inv, e.y * inv);
            h2[1] = __floats2half2_rn(e.z * inv, e.w * inv);
            *(ulonglong1*)(op + 4 * i) = *(ulonglong1*)h2;
        }
    }
    {
        const int i = (n4 << 2) + tid;
        if (i < n) op[i] = __float2half_rn(et * inv);
    }
    const fp16 z = __float2half_rn(0.f);
    for (int i = n + tid; i < tb; i += 256) op[i] = z;
}

// ---------------- launch ----------------------------------------------------
extern "C" void kernel_launch(void* const* d_in, const int* in_sizes, int n_in,
                              void* d_out, int out_size)
{
    const float* x     = (const float*)d_in[0];
    const float* gamma = (const float*)d_in[2];
    const float* beta  = (const float*)d_in[3];
    const float* Wqkv  = (const float*)d_in[4];
    const float* Wproj = (const float*)d_in[5];
    float* out = (float*)d_out;

    bf16 *xnh, *xnl, *wqh, *wql, *wph, *wpl, *ath, *atl;
    fp16 *qkv16, *vt16, *p16;
    float* S;
    cudaGetSymbolAddress((void**)&xnh, g_xn_h);    cudaGetSymbolAddress((void**)&xnl, g_xn_l);
    cudaGetSymbolAddress((void**)&wqh, g_wqkvT_h); cudaGetSymbolAddress((void**)&wql, g_wqkvT_l);
    cudaGetSymbolAddress((void**)&wph, g_wprojT_h); cudaGetSymbolAddress((void**)&wpl, g_wprojT_l);
    cudaGetSymbolAddress((void**)&qkv16, g_qkv16);
    cudaGetSymbolAddress((void**)&vt16,  g_vt16);
    cudaGetSymbolAddress((void**)&S,   g_S);
    cudaGetSymbolAddress((void**)&p16, g_P16);
    cudaGetSymbolAddress((void**)&ath, g_att_h);   cudaGetSymbolAddress((void**)&atl, g_att_l);

    cudaFuncSetAttribute(gemm_mma,   cudaFuncAttributeMaxDynamicSharedMemorySize, GSMEM);
    cudaFuncSetAttribute(gemm_mma16, cudaFuncAttributeMaxDynamicSharedMemorySize, GSMEM16);

    // 1. LN -> hi/lo
    ln_kernel<<<BT_, 128>>>(x, gamma, beta, xnh, xnl);

    // 2. weight transposes (independent)
    wtrans_kernel<<<dim3(N3_ / 32, D_ / 32), dim3(32, 8)>>>(Wqkv, D_, N3_, wqh, wql);
    wtrans_kernel<<<dim3(D_ / 32, D_ / 32), dim3(32, 8)>>>(Wproj, D_, D_, wph, wpl);

    // 3. QKV (bf16x3): xn @ WqkvT^T -> qkv fp16 single [16384,1536]
    gemm_mma<<<dim3(N3_ / 128, BT_ / 128, 1), 256, GSMEM>>>(
        xnh, xnl, D_, 0, wqh, wql, D_, 0,
        nullptr, nullptr, nullptr, qkv16, N3_, 0, D_, 1.0f, /*flags=*/8);

    // 4. V transpose per batch (fp16)
    vtrans_kernel<<<dim3(T_ / 32, D_ / 32, B_), dim3(32, 8)>>>(qkv16, vt16);

    // 5. scores (fp16x1): Q @ K^T * scale -> S f32 (causal tile skip)
    gemm_mma16<<<dim3(T_ / 128, T_ / 128, B_), 256, GSMEM16>>>(
        qkv16 + 0,  N3_, (ll)T_ * N3_,
        qkv16 + D_, N3_, (ll)T_ * N3_,
        S, nullptr, nullptr, T_, (ll)T_ * T_, D_, SCALE_QK, /*flags=*/1);

    // 6. softmax -> P fp16 (zero-fill to tile edge)
    softmax_kernel<<<BT_, 256>>>(S, p16);

    // 7. PV (fp16x1): P @ VT^T -> att bf16 hi/lo (causal kbound)
    gemm_mma16<<<dim3(D_ / 128, T_ / 128, B_), 256, GSMEM16>>>(
        p16, T_, (ll)T_ * T_,
        vt16, T_, (ll)D_ * T_,
        nullptr, ath, atl, D_, (ll)T_ * D_, T_, 1.0f, /*flags=*/2 | 4);

    // 8. projection (bf16x3): att @ WprojT^T -> out f32
    gemm_mma<<<dim3(D_ / 128, BT_ / 128, 1), 256, GSMEM>>>(
        ath, atl, D_, 0, wph, wpl, D_, 0,
        out, nullptr, nullptr, nullptr, D_, 0, D_, 1.0f, /*flags=*/0);
}

// round 12
// speedup vs baseline: 5.7133x; 1.3257x over previous
#include <cuda_runtime.h>
#include <cuda_fp16.h>
#include <cstdint>
#include <math.h>

// Problem constants
#define B_  4
#define T_  4096
#define D_  512
#define BT_ (B_ * T_)          // 16384
#define N3_ (3 * D_)           // 1536
#define EPS_LN 1e-5f
#define SCALE_QK 0.04419417382415922f   // 1/sqrt(512)

typedef long long ll;
typedef __half fp16;

// ---------------- scratch (device globals) ----------------------------------
__device__ fp16  g_xn16 [(ll)BT_ * D_];       // LN output fp16
__device__ fp16  g_wqkvT16 [(ll)N3_ * D_];    // Wqkv^T fp16
__device__ fp16  g_wprojT16[(ll)D_ * D_];     // Wproj^T fp16
__device__ fp16  g_qkv16[(ll)BT_ * N3_];      // Q,K,V fp16
__device__ fp16  g_vt16 [(ll)B_ * D_ * T_];   // V transposed fp16
__device__ float g_S    [(ll)B_ * T_ * T_];   // scores f32
__device__ fp16  g_P16  [(ll)B_ * T_ * T_];   // probs fp16
__device__ fp16  g_att16[(ll)BT_ * D_];       // attention out fp16

// ---------------- PTX helpers (all base sm_103-safe) -------------------------
__device__ __forceinline__ uint32_t smem_u32(const void* p) {
    uint32_t a;
    asm("{ .reg .u64 t; cvta.to.shared.u64 t, %1; cvt.u32.u64 %0, t; }" : "=r"(a) : "l"(p));
    return a;
}
__device__ __forceinline__ void cp16(uint32_t d, const void* g) {
    asm volatile("cp.async.cg.shared.global [%0], [%1], 16;" :: "r"(d), "l"(g) : "memory");
}
#define CP_COMMIT() asm volatile("cp.async.commit_group;" ::: "memory")
#define CP_WAIT(n)  asm volatile("cp.async.wait_group %0;" :: "n"(n) : "memory")

#define LDSM4(r0, r1, r2, r3, a) \
    asm volatile("ldmatrix.sync.aligned.m8n8.x4.shared.b16 {%0,%1,%2,%3}, [%4];" \
        : "=r"(r0), "=r"(r1), "=r"(r2), "=r"(r3) : "r"(a))

#define MMA16816H(d, a, b) \
    asm volatile("mma.sync.aligned.m16n8k16.row.col.f32.f16.f16.f32 " \
        "{%0,%1,%2,%3}, {%4,%5,%6,%7}, {%8,%9}, {%0,%1,%2,%3};" \
        : "+f"((d)[0]), "+f"((d)[1]), "+f"((d)[2]), "+f"((d)[3]) \
        : "r"((a)[0]), "r"((a)[1]), "r"((a)[2]), "r"((a)[3]), "r"((b)[0]), "r"((b)[1]))

// ---------------- LayerNorm -> fp16 ------------------------------------------
__global__ void ln_kernel(const float* __restrict__ x,
                          const float* __restrict__ gamma,
                          const float* __restrict__ beta,
                          fp16* __restrict__ xn)
{
    const ll row = blockIdx.x;
    const int tid = threadIdx.x;             // 0..127
    float4 v = ((const float4*)(x + row * D_))[tid];

    float s  = v.x + v.y + v.z + v.w;
    float ss = v.x*v.x + v.y*v.y + v.z*v.z + v.w*v.w;
    #pragma unroll
    for (int o = 16; o > 0; o >>= 1) {
        s  += __shfl_xor_sync(0xffffffffu, s,  o);
        ss += __shfl_xor_sync(0xffffffffu, ss, o);
    }
    __shared__ float rs[4], rss[4];
    if ((tid & 31) == 0) { rs[tid >> 5] = s; rss[tid >> 5] = ss; }
    __syncthreads();
    s  = rs[0] + rs[1] + rs[2] + rs[3];
    ss = rss[0] + rss[1] + rss[2] + rss[3];

    const float mu   = s * (1.0f / D_);
    const float var  = ss * (1.0f / D_) - mu * mu;
    const float rstd = rsqrtf(var + EPS_LN);

    float4 g = ((const float4*)gamma)[tid];
    float4 b = ((const float4*)beta)[tid];
    __half2 h2[2];
    h2[0] = __floats2half2_rn((v.x - mu) * rstd * g.x + b.x,
                              (v.y - mu) * rstd * g.y + b.y);
    h2[1] = __floats2half2_rn((v.z - mu) * rstd * g.z + b.z,
                              (v.w - mu) * rstd * g.w + b.w);
    *(ulonglong1*)(xn + row * D_ + tid * 4) = *(ulonglong1*)h2;
}

// ---------------- weight transpose-convert: W[K,N] f32 -> Wt[N,K] fp16 -------
__global__ void wtrans_kernel(const float* __restrict__ W, int K, int N,
                              fp16* __restrict__ Tw)
{
    __shared__ float t[32][33];
    const int n0 = blockIdx.x * 32, k0 = blockIdx.y * 32;
    const int tx = threadIdx.x, ty = threadIdx.y;
    #pragma unroll
    for (int i = 0; i < 32; i += 8)
        t[ty + i][tx] = W[(ll)(k0 + ty + i) * N + n0 + tx];
    __syncthreads();
    #pragma unroll
    for (int i = 0; i < 32; i += 8)
        Tw[(ll)(n0 + ty + i) * K + k0 + tx] = __float2half_rn(t[tx][ty + i]);
}

// ---------------- V transpose: qkv16 [BT,1536] -> VT fp16 [B,512,T] ----------
__global__ void vtrans_kernel(const fp16* __restrict__ q16, fp16* __restrict__ vt)
{
    __shared__ fp16 t[32][33];
    const int s0 = blockIdx.x * 32, c0 = blockIdx.y * 32, b = blockIdx.z;
    const int tx = threadIdx.x, ty = threadIdx.y;
    const ll qb = ((ll)b * T_) * N3_ + 2 * D_;
    #pragma unroll
    for (int i = 0; i < 32; i += 8)
        t[ty + i][tx] = q16[qb + (ll)(s0 + ty + i) * N3_ + c0 + tx];
    __syncthreads();
    const ll vb = (ll)b * D_ * T_;
    #pragma unroll
    for (int i = 0; i < 32; i += 8)
        vt[vb + (ll)(c0 + ty + i) * T_ + s0 + tx] = t[tx][ty + i];
}

// ---------------- fp16 x1 NT GEMM (all four GEMMs) ---------------------------
// C[M,N] = alpha * A[M,K] @ B[N,K]^T, fp16 operands, fp32 accum.
// flags: 1 = causal tile skip, 2 = causal kbound, 8 = fp16 output (else f32)
// Tile: CTA 128x128, BK=32, 8 warps (2x4), warp tile 64x32, 4-stage cp.async.
#define MAT_B 8192                 // 128 rows * 32 k * 2B
#define NSTAGE 4
#define STG16_B (2 * MAT_B)        // A, B = 16 KB
#define GSMEM16 (NSTAGE * STG16_B) // 64 KB

__global__ __launch_bounds__(256, 2)
void gemm_mma16(const fp16* __restrict__ A, int lda, ll sA,
                const fp16* __restrict__ Bm, int ldb, ll sB,
                float* __restrict__ Cf, fp16* __restrict__ C16,
                int ldc, ll sC, int K, float alpha, int flags)
{
    const int bx = blockIdx.x, by = blockIdx.y, bz = blockIdx.z;
    if ((flags & 1) && bx > by) return;

    extern __shared__ char smem[];
    const uint32_t sbase = smem_u32(smem);
    const int tid = threadIdx.x;
    const int wid = tid >> 5, lane = tid & 31;
    const int wm = wid >> 2, wn = wid & 3;

    const int m0 = by * 128, n0 = bx * 128;
    int Keff = K;
    if (flags & 2) { int kb = m0 + 128; Keff = kb < K ? kb : K; }
    const int NK = Keff / 32;     // >= 4 for all call sites

    const char* srcA = (const char*)(A  + (ll)bz * sA + (ll)m0 * lda);
    const char* srcB = (const char*)(Bm + (ll)bz * sB + (ll)n0 * ldb);
    const ll strA = (ll)lda * 2, strB = (ll)ldb * 2;

    const int cid0 = tid * 2;
    const int lrow0 = cid0 >> 2, lc0 = cid0 & 3;
    const int lrow1 = (cid0 + 1) >> 2, lc1 = (cid0 + 1) & 3;
    const uint32_t ldoff0 = lrow0 * 64 + (lc0 ^ ((lrow0 >> 1) & 3)) * 16;
    const uint32_t ldoff1 = lrow1 * 64 + (lc1 ^ ((lrow1 >> 1) & 3)) * 16;

    auto load_stage = [&](int s, int k0) {
        const uint32_t db = sbase + s * STG16_B;
        const ll ko = (ll)k0 * 2;
        cp16(db + 0 * MAT_B + ldoff0, srcA + (ll)lrow0 * strA + ko + lc0 * 16);
        cp16(db + 0 * MAT_B + ldoff1, srcA + (ll)lrow1 * strA + ko + lc1 * 16);
        cp16(db + 1 * MAT_B + ldoff0, srcB + (ll)lrow0 * strB + ko + lc0 * 16);
        cp16(db + 1 * MAT_B + ldoff1, srcB + (ll)lrow1 * strB + ko + lc1 * 16);
    };

    uint32_t aOff[4], bOff[2];
    {
        const int l15 = lane & 15, l4 = lane >> 4;
        #pragma unroll
        for (int mt = 0; mt < 4; mt++) {
            int r = wm * 64 + mt * 16 + l15;
            aOff[mt] = r * 64 + ((l4 ^ ((r >> 1) & 3)) * 16);
        }
        const int l7 = lane & 7, l3 = (lane >> 3) & 1;
        #pragma unroll
        for (int p = 0; p < 2; p++) {
            int r = wn * 32 + (p * 2 + l4) * 8 + l7;
            bOff[p] = r * 64 + ((l3 ^ ((r >> 1) & 3)) * 16);
        }
    }

    float acc[4][4][4] = {};

    load_stage(0, 0);  CP_COMMIT();
    load_stage(1, 32); CP_COMMIT();
    load_stage(2, 64); CP_COMMIT();

    int stage = 0;
    for (int c = 0; c < NK; ++c) {
        if (c + 2 < NK)      { CP_WAIT(2); }
        else if (c + 1 < NK) { CP_WAIT(1); }
        else                 { CP_WAIT(0); }
        __syncthreads();                 // all warps done with stage (c-1)%4
        if (c + 3 < NK) {                // its slot (c+3)%4 == (c-1)%4 is free
            int ns = stage + 3; if (ns >= NSTAGE) ns -= NSTAGE;
            load_stage(ns, (c + 3) * 32);
            CP_COMMIT();
        }

        const uint32_t sb = sbase + stage * STG16_B;
        #pragma unroll
        for (int ks = 0; ks < 2; ks++) {
            const uint32_t kx = ks * 32;
            uint32_t bfr[4][2];
            #pragma unroll
            for (int p = 0; p < 2; p++) {
                LDSM4(bfr[2*p][0], bfr[2*p][1], bfr[2*p+1][0], bfr[2*p+1][1], sb + 1 * MAT_B + (bOff[p] ^ kx));
            }
            #pragma unroll
            for (int mt = 0; mt < 4; mt++) {
                uint32_t afr[4];
                LDSM4(afr[0], afr[1], afr[2], afr[3], sb + 0 * MAT_B + (aOff[mt] ^ kx));
                #pragma unroll
                for (int nt = 0; nt < 4; nt++)
                    MMA16816H(acc[mt][nt], afr, bfr[nt]);
            }
        }
        if (++stage >= NSTAGE) stage = 0;
    }

    // epilogue
    const int g = lane >> 2, tg = lane & 3;
    #pragma unroll
    for (int mt = 0; mt < 4; mt++) {
        const int r = m0 + wm * 64 + mt * 16 + g;
        #pragma unroll
        for (int nt = 0; nt < 4; nt++) {
            const int col = n0 + wn * 32 + nt * 8 + 2 * tg;
            float v0 = alpha * acc[mt][nt][0];
            float v1 = alpha * acc[mt][nt][1];
            float v2 = alpha * acc[mt][nt][2];
            float v3 = alpha * acc[mt][nt][3];
            if (flags & 8) {
                *(__half2*)(C16 + (ll)bz * sC + (ll)r * ldc + col)       = __floats2half2_rn(v0, v1);
                *(__half2*)(C16 + (ll)bz * sC + (ll)(r + 8) * ldc + col) = __floats2half2_rn(v2, v3);
            } else {
                float2 p0, p1;
                p0.x = v0; p0.y = v1; p1.x = v2; p1.y = v3;
                *(float2*)(Cf + (ll)bz * sC + (ll)r * ldc + col) = p0;
                *(float2*)(Cf + (ll)bz * sC + (ll)(r + 8) * ldc + col) = p1;
            }
        }
    }
}

// ---------------- causal softmax: S f32 -> P fp16 (vectorized) ---------------
__global__ void softmax_kernel(const float* __restrict__ S, fp16* __restrict__ P)
{
    const ll row = blockIdx.x;
    const int b = (int)(row >> 12);
    const int t = (int)(row & (T_ - 1));
    const float* p = S + ((ll)b * T_ + t) * T_;
    fp16* op = P + ((ll)b * T_ + t) * T_;
    const int n  = t + 1;                 // valid entries
    const int n4 = n >> 2;                // full float4 count
    const int tb = ((t >> 7) + 1) << 7;   // zero-fill to 128-tile edge
    const int tid = threadIdx.x;
    const float4* p4 = (const float4*)p;

    __shared__ float redm[8], reds[8];

    float m = -3.402823466e38f;
    #pragma unroll
    for (int it = 0; it < 4; it++) {
        const int i = tid + it * 256;
        if (i < n4) {
            float4 v = p4[i];
            m = fmaxf(m, fmaxf(fmaxf(v.x, v.y), fmaxf(v.z, v.w)));
        }
    }
    for (int i = (n4 << 2) + tid; i < n; i += 256) m = fmaxf(m, p[i]);
    #pragma unroll
    for (int o = 16; o > 0; o >>= 1) m = fmaxf(m, __shfl_xor_sync(0xffffffffu, m, o));
    if ((tid & 31) == 0) redm[tid >> 5] = m;
    __syncthreads();
    m = redm[0];
    #pragma unroll
    for (int i = 1; i < 8; i++) m = fmaxf(m, redm[i]);

    float4 ev4[4];
    float et = 0.f;
    float s = 0.f;
    #pragma unroll
    for (int it = 0; it < 4; it++) {
        const int i = tid + it * 256;
        if (i < n4) {
            float4 v = p4[i];
            float4 e;
            e.x = __expf(v.x - m); e.y = __expf(v.y - m);
            e.z = __expf(v.z - m); e.w = __expf(v.w - m);
            ev4[it] = e;
            s += e.x + e.y + e.z + e.w;
        }
    }
    {
        const int i = (n4 << 2) + tid;
        if (i < n) { et = __expf(p[i] - m); s += et; }
    }
    #pragma unroll
    for (int o = 16; o > 0; o >>= 1) s += __shfl_xor_sync(0xffffffffu, s, o);
    if ((tid & 31) == 0) reds[tid >> 5] = s;
    __syncthreads();
    s = reds[0] + reds[1] + reds[2] + reds[3] + reds[4] + reds[5] + reds[6] + reds[7];
    const float inv = 1.0f / s;

    #pragma unroll
    for (int it = 0; it < 4; it++) {
        const int i = tid + it * 256;
        if (i < n4) {
            float4 e = ev4[it];
            __half2 h2[2];
            h2[0] = __floats2half2_rn(e.x * inv, e.y * inv);
            h2[1] = __floats2half2_rn(e.z * inv, e.w * inv);
            *(ulonglong1*)(op + 4 * i) = *(ulonglong1*)h2;
        }
    }
    {
        const int i = (n4 << 2) + tid;
        if (i < n) op[i] = __float2half_rn(et * inv);
    }
    const fp16 z = __float2half_rn(0.f);
    for (int i = n + tid; i < tb; i += 256) op[i] = z;
}

// ---------------- launch ----------------------------------------------------
extern "C" void kernel_launch(void* const* d_in, const int* in_sizes, int n_in,
                              void* d_out, int out_size)
{
    const float* x     = (const float*)d_in[0];
    const float* gamma = (const float*)d_in[2];
    const float* beta  = (const float*)d_in[3];
    const float* Wqkv  = (const float*)d_in[4];
    const float* Wproj = (const float*)d_in[5];
    float* out = (float*)d_out;

    fp16 *xn16, *wq16, *wp16, *qkv16, *vt16, *p16, *att16;
    float* S;
    cudaGetSymbolAddress((void**)&xn16,  g_xn16);
    cudaGetSymbolAddress((void**)&wq16,  g_wqkvT16);
    cudaGetSymbolAddress((void**)&wp16,  g_wprojT16);
    cudaGetSymbolAddress((void**)&qkv16, g_qkv16);
    cudaGetSymbolAddress((void**)&vt16,  g_vt16);
    cudaGetSymbolAddress((void**)&S,     g_S);
    cudaGetSymbolAddress((void**)&p16,   g_P16);
    cudaGetSymbolAddress((void**)&att16, g_att16);

    cudaFuncSetAttribute(gemm_mma16, cudaFuncAttributeMaxDynamicSharedMemorySize, GSMEM16);

    // 1. LN -> fp16
    ln_kernel<<<BT_, 128>>>(x, gamma, beta, xn16);

    // 2. weight transposes (independent)
    wtrans_kernel<<<dim3(N3_ / 32, D_ / 32), dim3(32, 8)>>>(Wqkv, D_, N3_, wq16);
    wtrans_kernel<<<dim3(D_ / 32, D_ / 32), dim3(32, 8)>>>(Wproj, D_, D_, wp16);

    // 3. QKV: xn @ WqkvT^T -> qkv fp16 [16384,1536]
    gemm_mma16<<<dim3(N3_ / 128, BT_ / 128, 1), 256, GSMEM16>>>(
        xn16, D_, 0, wq16, D_, 0,
        nullptr, qkv16, N3_, 0, D_, 1.0f, /*flags=*/8);

    // 4. V transpose per batch (fp16)
    vtrans_kernel<<<dim3(T_ / 32, D_ / 32, B_), dim3(32, 8)>>>(qkv16, vt16);

    // 5. scores: Q @ K^T * scale -> S f32 (causal tile skip)
    gemm_mma16<<<dim3(T_ / 128, T_ / 128, B_), 256, GSMEM16>>>(
        qkv16 + 0,  N3_, (ll)T_ * N3_,
        qkv16 + D_, N3_, (ll)T_ * N3_,
        S, nullptr, T_, (ll)T_ * T_, D_, SCALE_QK, /*flags=*/1);

    // 6. softmax -> P fp16 (zero-fill to tile edge)
    softmax_kernel<<<BT_, 256>>>(S, p16);

    // 7. PV: P @ VT^T -> att fp16 (causal kbound)
    gemm_mma16<<<dim3(D_ / 128, T_ / 128, B_), 256, GSMEM16>>>(
        p16, T_, (ll)T_ * T_,
        vt16, T_, (ll)D_ * T_,
        nullptr, att16, D_, (ll)T_ * D_, T_, 1.0f, /*flags=*/2 | 8);

    // 8. projection: att @ WprojT^T -> out f32
    gemm_mma16<<<dim3(D_ / 128, BT_ / 128, 1), 256, GSMEM16>>>(
        att16, D_, 0, wp16, D_, 0,
        out, nullptr, D_, 0, D_, 1.0f, /*flags=*/0);
}